// round 13
// baseline (speedup 1.0000x reference)
#include <cuda_runtime.h>
#include <cuda_fp16.h>
#include <cstdint>

#define FULLMASK 0xffffffffu

// Problem sizes (fixed by the dataset)
#define CN 50000
#define CE 800000

// ---------------- scratch (device globals; no cudaMalloc allowed) -------------
__device__ __align__(16) float g_Ah[CN * 64];
__device__ __align__(16) __half g_BCh[CN * 128]; // fp16 interleaved [B0,C0,B1,C1,...]
__device__ __align__(16) __half g_Dh[CN * 64];   // fp16
__device__ __align__(16) float g_h2[CN * 64];
__device__ __align__(16) __half g_sxh[CN * 128]; // fp16 interleaved [ss0,ssh0,ss1,ssh1,...]
__device__ __align__(16) __half g_e2h[CE * 64];  // e after residual, fp16
__device__ float g_stats[4 * 128]; // [set][sum(64) | sumsq(64)]

// ================= mma.sync / ldmatrix helpers (base sm_103 ISA) ===============
__device__ __forceinline__ uint32_t smem_u32(const void* p) {
    return (uint32_t)__cvta_generic_to_shared(p);
}

__device__ __forceinline__ void ldsm_x4(uint32_t (&r)[4], uint32_t addr) {
    asm volatile("ldmatrix.sync.aligned.m8n8.x4.shared.b16 {%0,%1,%2,%3}, [%4];"
                 : "=r"(r[0]), "=r"(r[1]), "=r"(r[2]), "=r"(r[3]) : "r"(addr));
}

// x4 transposed: loads TWO n8k16 B fragments at once.
__device__ __forceinline__ void ldsm_x4t(uint32_t (&b)[4], uint32_t addr) {
    asm volatile("ldmatrix.sync.aligned.m8n8.x4.trans.shared.b16 {%0,%1,%2,%3}, [%4];"
                 : "=r"(b[0]), "=r"(b[1]), "=r"(b[2]), "=r"(b[3]) : "r"(addr));
}

__device__ __forceinline__ void mma_16816(float (&c)[4], const uint32_t (&a)[4],
                                          uint32_t b0, uint32_t b1) {
    asm volatile(
        "mma.sync.aligned.m16n8k16.row.col.f32.f16.f16.f32 "
        "{%0,%1,%2,%3}, {%4,%5,%6,%7}, {%8,%9}, {%0,%1,%2,%3};"
        : "+f"(c[0]), "+f"(c[1]), "+f"(c[2]), "+f"(c[3])
        : "r"(a[0]), "r"(a[1]), "r"(a[2]), "r"(a[3]), "r"(b0), "r"(b1));
}

// helper: compute per-block BN scale/shift into smem (64 threads participate)
__device__ __forceinline__ void bn_fold_smem(int tid, int set,
                                             const float* __restrict__ gamma,
                                             const float* __restrict__ beta,
                                             float inv, float* sc, float* sh) {
    if (tid < 64) {
        float mean = g_stats[set * 128 + tid] * inv;
        float var = g_stats[set * 128 + 64 + tid] * inv - mean * mean;
        float s = gamma[tid] * rsqrtf(var + 1e-5f);
        sc[tid] = s;
        sh[tid] = beta[tid] - mean * s;
    }
}

// ---------------- zero stats accumulators --------------------------------------
__global__ void k_zero() {
    g_stats[threadIdx.x] = 0.f;
}

// ---------------- column mean/var stats for BOTH h and e -----------------------
// blocks [0,512) -> h (set 0); blocks [512, grid) -> e (set 1)
__global__ __launch_bounds__(256) void k_stats2(const float* __restrict__ h, int hrows,
                                                const float* __restrict__ e, int erows) {
    __shared__ float ssum[64], ssq[64];
    int tid = threadIdx.x;
    bool isE = blockIdx.x >= 512;
    const float* __restrict__ x = isE ? e : h;
    int rows = isE ? erows : hrows;
    int set = isE ? 1 : 0;
    int bid = isE ? blockIdx.x - 512 : blockIdx.x;
    int nb = isE ? gridDim.x - 512 : 512;
    if (tid < 64) { ssum[tid] = 0.f; ssq[tid] = 0.f; }
    __syncthreads();
    int cg = tid & 15;
    int r = (bid * 256 + tid) >> 4;
    int rstride = (nb * 256) >> 4;
    float4 s = make_float4(0, 0, 0, 0), q = make_float4(0, 0, 0, 0);
    for (; r < rows; r += rstride) {
        float4 v = *(const float4*)(x + (size_t)r * 64 + cg * 4);
        s.x += v.x; s.y += v.y; s.z += v.z; s.w += v.w;
        q.x += v.x * v.x; q.y += v.y * v.y; q.z += v.z * v.z; q.w += v.w * v.w;
    }
    atomicAdd(&ssum[cg * 4 + 0], s.x); atomicAdd(&ssum[cg * 4 + 1], s.y);
    atomicAdd(&ssum[cg * 4 + 2], s.z); atomicAdd(&ssum[cg * 4 + 3], s.w);
    atomicAdd(&ssq[cg * 4 + 0], q.x);  atomicAdd(&ssq[cg * 4 + 1], q.y);
    atomicAdd(&ssq[cg * 4 + 2], q.z);  atomicAdd(&ssq[cg * 4 + 3], q.w);
    __syncthreads();
    if (tid < 64) {
        atomicAdd(&g_stats[set * 128 + tid], ssum[tid]);
        atomicAdd(&g_stats[set * 128 + 64 + tid], ssq[tid]);
    }
}

// ---------------- node linears via mma ------------------------------------------
// weight slot order in sW cols: [B | C | A | D]. Writes g_BCh (fp16 interleaved),
// g_Dh (fp16), g_Ah (fp32); zeros g_sxh for its rows.
__global__ __launch_bounds__(256) void k_node_mma(
    const float* __restrict__ h,
    const float* __restrict__ Aw, const float* __restrict__ Bw,
    const float* __restrict__ Cw, const float* __restrict__ Dw,
    const float* __restrict__ Ab, const float* __restrict__ Bb,
    const float* __restrict__ Cb, const float* __restrict__ Db,
    const float* __restrict__ g1h, const float* __restrict__ b1h,
    float invN, int rows) {
    extern __shared__ char smraw[];
    __half* sW = (__half*)smraw;                         // [64][264]
    __half* sA = (__half*)(smraw + 64 * 264 * 2);        // 8 warps x [16][72]
    float* sc = (float*)(smraw + 64 * 264 * 2 + 8 * 16 * 72 * 2);
    float* sh = sc + 64;
    float* sBias = sh + 64;                              // [4][64] order B,C,A,D
    int tid = threadIdx.x, wid = tid >> 5, lane = tid & 31;

    bn_fold_smem(tid, 0, g1h, b1h, invN, sc, sh);
    __syncthreads();
    for (int i = tid; i < 4 * 4096; i += 256) {
        int m = i >> 12, idx = i & 4095, k = idx >> 6, n = idx & 63;
        const float* W = m == 0 ? Bw : m == 1 ? Cw : m == 2 ? Aw : Dw;
        sW[k * 264 + m * 64 + n] = __float2half(sc[k] * W[idx]);
    }
    {   // bias fold: tid -> (m, n), order B,C,A,D
        int m = tid >> 6, n = tid & 63;
        const float* W = m == 0 ? Bw : m == 1 ? Cw : m == 2 ? Aw : Dw;
        const float* bb = m == 0 ? Bb : m == 1 ? Cb : m == 2 ? Ab : Db;
        float acc = bb[n];
#pragma unroll 8
        for (int k = 0; k < 64; k++) acc += sh[k] * W[k * 64 + n];
        sBias[tid] = acc;
    }
    __syncthreads();

    __half* aBuf = sA + wid * 16 * 72;
    uint32_t aU = smem_u32(aBuf);
    uint32_t wU = smem_u32(sW);
    uint32_t aLd = aU + (uint32_t)(((lane & 15) * 72 + ((lane >> 4) << 3)) * 2);
    uint32_t bRow = lane & 15;
    uint32_t bColOff = (uint32_t)((lane >> 4) << 3);
    int cg = lane & 15, rsub = lane >> 4;
    int ntiles = (rows + 15) >> 4;
    for (int t = blockIdx.x * 8 + wid; t < ntiles; t += gridDim.x * 8) {
        int rbase = t << 4;
#pragma unroll
        for (int j = 0; j < 8; j++) {
            int rloc = rsub + j * 2;
            int row = rbase + rloc; if (row >= rows) row = rows - 1;
            float4 v = *(const float4*)(h + (size_t)row * 64 + cg * 4);
            __half* dp = aBuf + rloc * 72 + cg * 4;
            *(__half2*)dp = __floats2half2_rn(v.x, v.y);
            *(__half2*)(dp + 2) = __floats2half2_rn(v.z, v.w);
        }
        __syncwarp();
        uint32_t afr[4][4];
#pragma unroll
        for (int kt = 0; kt < 4; kt++) ldsm_x4(afr[kt], aLd + kt * 32);
        int r0 = rbase + (lane >> 2), r1 = r0 + 8;
#pragma unroll
        for (int p = 0; p < 2; p++) {
            float c[16][4];
#pragma unroll
            for (int nt = 0; nt < 16; nt++) { c[nt][0] = c[nt][1] = c[nt][2] = c[nt][3] = 0.f; }
#pragma unroll
            for (int ntp = 0; ntp < 8; ntp++) {
#pragma unroll
                for (int kt = 0; kt < 4; kt++) {
                    uint32_t b[4];
                    ldsm_x4t(b, wU + (uint32_t)(((kt * 16 + bRow) * 264 + p * 128 + ntp * 16 + bColOff) * 2));
                    mma_16816(c[2 * ntp],     afr[kt], b[0], b[1]);
                    mma_16816(c[2 * ntp + 1], afr[kt], b[2], b[3]);
                }
            }
            if (p == 0) {
                // B = c[nt], C = c[nt+8] -> fp16 interleaved g_BCh
#pragma unroll
                for (int nt = 0; nt < 8; nt++) {
                    int col = nt * 8 + 2 * (lane & 3);
                    float2 bB = *(const float2*)(sBias + col);
                    float2 bC = *(const float2*)(sBias + 64 + col);
                    if (r0 < rows) {
                        __half2 h0 = __floats2half2_rn(c[nt][0] + bB.x, c[nt + 8][0] + bC.x);
                        __half2 h1 = __floats2half2_rn(c[nt][1] + bB.y, c[nt + 8][1] + bC.y);
                        __half2* dp = (__half2*)(g_BCh + (size_t)r0 * 128 + 2 * col);
                        dp[0] = h0; dp[1] = h1;
                    }
                    if (r1 < rows) {
                        __half2 h0 = __floats2half2_rn(c[nt][2] + bB.x, c[nt + 8][2] + bC.x);
                        __half2 h1 = __floats2half2_rn(c[nt][3] + bB.y, c[nt + 8][3] + bC.y);
                        __half2* dp = (__half2*)(g_BCh + (size_t)r1 * 128 + 2 * col);
                        dp[0] = h0; dp[1] = h1;
                    }
                }
            } else {
                // A = c[0..7] (fp32), D = c[8..15] (fp16)
#pragma unroll
                for (int nt = 0; nt < 8; nt++) {
                    int col = nt * 8 + 2 * (lane & 3);
                    float2 bia = *(const float2*)(sBias + 128 + col);
                    if (r0 < rows)
                        *(float2*)(g_Ah + (size_t)r0 * 64 + col) =
                            make_float2(c[nt][0] + bia.x, c[nt][1] + bia.y);
                    if (r1 < rows)
                        *(float2*)(g_Ah + (size_t)r1 * 64 + col) =
                            make_float2(c[nt][2] + bia.x, c[nt][3] + bia.y);
                }
#pragma unroll
                for (int nt = 8; nt < 16; nt++) {
                    int col = (nt & 7) * 8 + 2 * (lane & 3);
                    float2 bia = *(const float2*)(sBias + 192 + col);
                    if (r0 < rows)
                        *(__half2*)(g_Dh + (size_t)r0 * 64 + col) =
                            __floats2half2_rn(c[nt][0] + bia.x, c[nt][1] + bia.y);
                    if (r1 < rows)
                        *(__half2*)(g_Dh + (size_t)r1 * 64 + col) =
                            __floats2half2_rn(c[nt][2] + bia.x, c[nt][3] + bia.y);
                }
            }
        }
        // zero g_sxh for rows r0, r1 (row = 128 half = 256B; 4 x (4 lanes x 16B))
        uint4 z4 = make_uint4(0u, 0u, 0u, 0u);
#pragma unroll
        for (int nt = 0; nt < 4; nt++) {
            int off = nt * 32 + (lane & 3) * 8;
            if (r0 < rows) *(uint4*)(g_sxh + (size_t)r0 * 128 + off) = z4;
            if (r1 < rows) *(uint4*)(g_sxh + (size_t)r1 * 128 + off) = z4;
        }
        __syncwarp();
    }
}

// ---------------- fused edge kernel: Ee GEMM + gates + segment sums ------------
// 128 threads, 8 CTAs/SM target (64 regs). Split-N epilogue; fp16 gathers;
// residual e from the fp16 staged tile; e2 stored fp16; half2 atomics.
__global__ void __launch_bounds__(128, 8) k_edge_mma(
    const float* __restrict__ e, const int* __restrict__ src, const int* __restrict__ dst,
    const float* __restrict__ Ew, const float* __restrict__ Eb,
    const float* __restrict__ g1e, const float* __restrict__ b1e,
    float invE, int ecount) {
    __shared__ __half sW[64 * 72];
    __shared__ __half sA[4][16 * 72];
    __shared__ float sc[64], sh[64], sb[64];
    int tid = threadIdx.x, wid = tid >> 5, lane = tid & 31;

    bn_fold_smem(tid, 1, g1e, b1e, invE, sc, sh);
    __syncthreads();
    for (int i = tid; i < 4096; i += 128) {
        int k = i >> 6, n = i & 63;
        sW[k * 72 + n] = __float2half(sc[k] * Ew[i]);
    }
    if (tid < 64) {
        float acc = Eb[tid];
#pragma unroll 8
        for (int k = 0; k < 64; k++) acc += sh[k] * Ew[k * 64 + tid];
        sb[tid] = acc;
    }
    __syncthreads();

    uint32_t aU = smem_u32(&sA[wid][0]);
    uint32_t wU = smem_u32(sW);
    uint32_t aLd = aU + (uint32_t)(((lane & 15) * 72 + ((lane >> 4) << 3)) * 2);
    uint32_t bRow = lane & 15;
    uint32_t bColOff = (uint32_t)((lane >> 4) << 3);
    int cg = lane & 15, rsub = lane >> 4;
    int rq = lane >> 2;  // epilogue local row
    int ntiles = ecount >> 4;
    for (int t = blockIdx.x * 4 + wid; t < ntiles; t += gridDim.x * 4) {
        int ebase = t << 4;
#pragma unroll
        for (int j = 0; j < 8; j++) {
            int rloc = rsub + j * 2;
            float4 v = *(const float4*)(e + (size_t)(ebase + rloc) * 64 + cg * 4);
            __half* dp = &sA[wid][rloc * 72 + cg * 4];
            *(__half2*)dp = __floats2half2_rn(v.x, v.y);
            *(__half2*)(dp + 2) = __floats2half2_rn(v.z, v.w);
        }
        __syncwarp();
        uint32_t afr[4][4];
#pragma unroll
        for (int kt = 0; kt < 4; kt++) ldsm_x4(afr[kt], aLd + kt * 32);
        int r0 = ebase + rq, r1 = r0 + 8;
        int sI0 = src[r0], dI0 = dst[r0], sI1 = src[r1], dI1 = dst[r1];
#pragma unroll
        for (int half = 0; half < 2; half++) {
            float c[4][4];
#pragma unroll
            for (int nt = 0; nt < 4; nt++) { c[nt][0] = c[nt][1] = c[nt][2] = c[nt][3] = 0.f; }
#pragma unroll
            for (int ntp = 0; ntp < 2; ntp++) {
#pragma unroll
                for (int kt = 0; kt < 4; kt++) {
                    uint32_t b[4];
                    ldsm_x4t(b, wU + (uint32_t)(((kt * 16 + bRow) * 72 + (half * 2 + ntp) * 16 + bColOff) * 2));
                    mma_16816(c[2 * ntp],     afr[kt], b[0], b[1]);
                    mma_16816(c[2 * ntp + 1], afr[kt], b[2], b[3]);
                }
            }
#pragma unroll
            for (int nt = 0; nt < 4; nt++) {
                int c0 = (half * 4 + nt) * 8 + 2 * (lane & 3);
                float2 bia = *(const float2*)(sb + c0);
                // fp16 interleaved gathers: [B0,C0,B1,C1]
                uint2 raw0 = *(const uint2*)(g_BCh + (size_t)sI0 * 128 + 2 * c0);
                uint2 raw1 = *(const uint2*)(g_BCh + (size_t)sI1 * 128 + 2 * c0);
                float2 bc00 = __half22float2(*(__half2*)&raw0.x);  // (B0, C0)
                float2 bc01 = __half22float2(*(__half2*)&raw0.y);  // (B1, C1)
                float2 bc10 = __half22float2(*(__half2*)&raw1.x);
                float2 bc11 = __half22float2(*(__half2*)&raw1.y);
                float2 dh0 = __half22float2(*(const __half2*)(g_Dh + (size_t)dI0 * 64 + c0));
                float2 dh1 = __half22float2(*(const __half2*)(g_Dh + (size_t)dI1 * 64 + c0));
                float en00 = c[nt][0] + bia.x + bc00.y + dh0.x;
                float en01 = c[nt][1] + bia.y + bc01.y + dh0.y;
                float en10 = c[nt][2] + bia.x + bc10.y + dh1.x;
                float en11 = c[nt][3] + bia.y + bc11.y + dh1.y;
                // residual e from the fp16 staged tile (smem)
                float2 ev0 = __half22float2(*(__half2*)(&sA[wid][rq * 72 + c0]));
                float2 ev1 = __half22float2(*(__half2*)(&sA[wid][(rq + 8) * 72 + c0]));
                *(__half2*)(g_e2h + (size_t)r0 * 64 + c0) =
                    __floats2half2_rn(ev0.x + en00, ev0.y + en01);
                *(__half2*)(g_e2h + (size_t)r1 * 64 + c0) =
                    __floats2half2_rn(ev1.x + en10, ev1.y + en11);
                float sg00 = 1.f / (1.f + __expf(-en00));
                float sg01 = 1.f / (1.f + __expf(-en01));
                float sg10 = 1.f / (1.f + __expf(-en10));
                float sg11 = 1.f / (1.f + __expf(-en11));
                // half2 atomics: (ss, ssh) per column
                atomicAdd((__half2*)(g_sxh + (size_t)dI0 * 128 + 2 * c0),
                          __floats2half2_rn(sg00, bc00.x * sg00));
                atomicAdd((__half2*)(g_sxh + (size_t)dI0 * 128 + 2 * c0 + 2),
                          __floats2half2_rn(sg01, bc01.x * sg01));
                atomicAdd((__half2*)(g_sxh + (size_t)dI1 * 128 + 2 * c0),
                          __floats2half2_rn(sg10, bc10.x * sg10));
                atomicAdd((__half2*)(g_sxh + (size_t)dI1 * 128 + 2 * c0 + 2),
                          __floats2half2_rn(sg11, bc11.x * sg11));
            }
        }
        __syncwarp();
    }
}

// ---------------- h2 = h + Ah + ssh/(ss+eps) + set2 stats; e2 stats (set 3) ----
__global__ __launch_bounds__(256) void k_h2s(const float* __restrict__ h, int hrows, int erows) {
    int tid = threadIdx.x;
    if (blockIdx.x < 512) {
        int lane = tid & 31;
        int warp = (blockIdx.x * 256 + tid) >> 5;
        int nw = (512 * 256) >> 5;
        int c = lane * 2;
        float st_s0 = 0.f, st_s1 = 0.f, st_q0 = 0.f, st_q1 = 0.f;
        for (int r = warp; r < hrows; r += nw) {
            size_t o = (size_t)r * 64 + c;
            float2 hv = *(const float2*)(h + o);
            float2 ah = *(const float2*)(g_Ah + o);
            uint2 raw = *(const uint2*)(g_sxh + (size_t)r * 128 + 2 * c);
            float2 sx0 = __half22float2(*(__half2*)&raw.x);  // (ss0, ssh0)
            float2 sx1 = __half22float2(*(__half2*)&raw.y);  // (ss1, ssh1)
            float v0 = hv.x + ah.x + sx0.y / (sx0.x + 1e-10f);
            float v1 = hv.y + ah.y + sx1.y / (sx1.x + 1e-10f);
            *(float2*)(g_h2 + o) = make_float2(v0, v1);
            st_s0 += v0; st_q0 += v0 * v0;
            st_s1 += v1; st_q1 += v1 * v1;
        }
        atomicAdd(&g_stats[2 * 128 + c], st_s0);
        atomicAdd(&g_stats[2 * 128 + c + 1], st_s1);
        atomicAdd(&g_stats[2 * 128 + 64 + c], st_q0);
        atomicAdd(&g_stats[2 * 128 + 64 + c + 1], st_q1);
    } else {
        __shared__ float ssum[64], ssq[64];
        if (tid < 64) { ssum[tid] = 0.f; ssq[tid] = 0.f; }
        __syncthreads();
        int bid = blockIdx.x - 512, nb = gridDim.x - 512;
        int cg = tid & 15;
        int r = (bid * 256 + tid) >> 4;
        int rstride = (nb * 256) >> 4;
        float4 s = make_float4(0, 0, 0, 0), q = make_float4(0, 0, 0, 0);
        for (; r < erows; r += rstride) {
            uint2 raw = *(const uint2*)(g_e2h + (size_t)r * 64 + cg * 4);
            float2 f01 = __half22float2(*(__half2*)&raw.x);
            float2 f23 = __half22float2(*(__half2*)&raw.y);
            s.x += f01.x; s.y += f01.y; s.z += f23.x; s.w += f23.y;
            q.x += f01.x * f01.x; q.y += f01.y * f01.y;
            q.z += f23.x * f23.x; q.w += f23.y * f23.y;
        }
        atomicAdd(&ssum[cg * 4 + 0], s.x); atomicAdd(&ssum[cg * 4 + 1], s.y);
        atomicAdd(&ssum[cg * 4 + 2], s.z); atomicAdd(&ssum[cg * 4 + 3], s.w);
        atomicAdd(&ssq[cg * 4 + 0], q.x);  atomicAdd(&ssq[cg * 4 + 1], q.y);
        atomicAdd(&ssq[cg * 4 + 2], q.z);  atomicAdd(&ssq[cg * 4 + 3], q.w);
        __syncthreads();
        if (tid < 64) {
            atomicAdd(&g_stats[3 * 128 + tid], ssum[tid]);
            atomicAdd(&g_stats[3 * 128 + 64 + tid], ssq[tid]);
        }
    }
}

// ---------------- FFN via mma.sync: out = x2 + relu(bn(x2)@W1+b1)@W2 + b2 ------
// 256 threads (8 warps), dynamic smem, 2 CTAs/SM. Residual from staged fp16.
// which==0: source g_h2 (fp32); which==1: source g_e2h (fp16 direct copy).
__global__ void __launch_bounds__(256) k_ffn_mma(
    int which,
    int set,    // 2 (h) or 3 (e)
    const float* __restrict__ W1, const float* __restrict__ b1,
    const float* __restrict__ W2, const float* __restrict__ b2,
    const float* __restrict__ gamma, const float* __restrict__ beta,
    float inv, int rows, float* __restrict__ out) {
    const int LDA = 72, LDB1 = 136, LDB2 = 72;
    extern __shared__ char smraw[];
    __half* sB1 = (__half*)smraw;                       // 17408 B
    __half* sB2 = (__half*)(smraw + 17408);             // 18432 B
    __half* sA  = (__half*)(smraw + 35840);             // 8 x [16*72] = 18432 B
    float* sb1 = (float*)(smraw + 54272);               // 512 B
    float* sb2 = (float*)(smraw + 54784);               // 256 B
    float* sc  = (float*)(smraw + 55040);               // 256 B
    float* sh  = (float*)(smraw + 55296);               // 256 B

    int tid = threadIdx.x, wid = tid >> 5, lane = tid & 31;
    bn_fold_smem(tid, set, gamma, beta, inv, sc, sh);
    __syncthreads();
    for (int i = tid; i < 64 * 128; i += 256) {
        int k = i >> 7, n = i & 127;
        sB1[k * LDB1 + n] = __float2half(sc[k] * W1[i]);
    }
    for (int i = tid; i < 128 * 64; i += 256) {
        int k = i >> 6, n = i & 63;
        sB2[k * LDB2 + n] = __float2half(W2[i]);
    }
    if (tid < 128) {   // bias1 fold
        float acc = b1[tid];
#pragma unroll 8
        for (int k = 0; k < 64; k++) acc += sh[k] * W1[k * 128 + tid];
        sb1[tid] = acc;
    }
    if (tid < 64) sb2[tid] = b2[tid];
    __syncthreads();

    __half* aBuf = sA + wid * 16 * 72;
    uint32_t aU = smem_u32(aBuf);
    uint32_t b1U = smem_u32(sB1);
    uint32_t b2U = smem_u32(sB2);
    int cg = lane & 15;
    uint32_t aLdAddr = aU + (uint32_t)(((lane & 15) * LDA + ((lane >> 4) << 3)) * 2);
    uint32_t bRow = (uint32_t)(lane & 15);
    uint32_t bColOff = (uint32_t)((lane >> 4) << 3);
    int rq = lane >> 2;

    int ngroups = (rows + 15) >> 4;
    int gw = blockIdx.x * 8 + wid;
    int gstride = gridDim.x * 8;
    for (int g = gw; g < ngroups; g += gstride) {
        int rbase = g << 4;
        int rsub = lane >> 4;
        if (which == 0) {
#pragma unroll
            for (int j = 0; j < 8; j++) {
                int rloc = rsub + j * 2;
                int row = rbase + rloc; if (row >= rows) row = rows - 1;
                float4 v = *(const float4*)(g_h2 + (size_t)row * 64 + cg * 4);
                __half* dstp = aBuf + rloc * LDA + cg * 4;
                *(__half2*)(dstp) = __floats2half2_rn(v.x, v.y);
                *(__half2*)(dstp + 2) = __floats2half2_rn(v.z, v.w);
            }
        } else {
#pragma unroll
            for (int j = 0; j < 8; j++) {
                int rloc = rsub + j * 2;
                int row = rbase + rloc; if (row >= rows) row = rows - 1;
                uint2 v = *(const uint2*)(g_e2h + (size_t)row * 64 + cg * 4);
                *(uint2*)(aBuf + rloc * LDA + cg * 4) = v;
            }
        }
        __syncwarp();

        uint32_t afr[4][4];
#pragma unroll
        for (int kt = 0; kt < 4; kt++)
            ldsm_x4(afr[kt], aLdAddr + (uint32_t)(kt * 16 * 2));

        float c1[16][4];
#pragma unroll
        for (int nt = 0; nt < 16; nt++) { c1[nt][0] = c1[nt][1] = c1[nt][2] = c1[nt][3] = 0.f; }
#pragma unroll
        for (int ntp = 0; ntp < 8; ntp++) {
#pragma unroll
            for (int kt = 0; kt < 4; kt++) {
                uint32_t b[4];
                ldsm_x4t(b, b1U + (uint32_t)((((kt * 16) + bRow) * LDB1 + ntp * 16 + bColOff) * 2));
                mma_16816(c1[2 * ntp],     afr[kt], b[0], b[1]);
                mma_16816(c1[2 * ntp + 1], afr[kt], b[2], b[3]);
            }
        }

        uint32_t a2[8][4];
#pragma unroll
        for (int nt = 0; nt < 16; nt++) {
            int n0 = nt * 8 + 2 * (lane & 3);
            float bx = sb1[n0], by = sb1[n0 + 1];
            __half2 lo = __floats2half2_rn(fmaxf(c1[nt][0] + bx, 0.f),
                                           fmaxf(c1[nt][1] + by, 0.f));
            __half2 hi = __floats2half2_rn(fmaxf(c1[nt][2] + bx, 0.f),
                                           fmaxf(c1[nt][3] + by, 0.f));
            int kt2 = nt >> 1, base = (nt & 1) * 2;
            a2[kt2][base]     = *reinterpret_cast<uint32_t*>(&lo);
            a2[kt2][base + 1] = *reinterpret_cast<uint32_t*>(&hi);
        }

        float c2[8][4];
#pragma unroll
        for (int nt = 0; nt < 8; nt++) { c2[nt][0] = c2[nt][1] = c2[nt][2] = c2[nt][3] = 0.f; }
#pragma unroll
        for (int ntp = 0; ntp < 4; ntp++) {
#pragma unroll
            for (int kt = 0; kt < 8; kt++) {
                uint32_t b[4];
                ldsm_x4t(b, b2U + (uint32_t)((((kt * 16) + bRow) * LDB2 + ntp * 16 + bColOff) * 2));
                mma_16816(c2[2 * ntp],     a2[kt], b[0], b[1]);
                mma_16816(c2[2 * ntp + 1], a2[kt], b[2], b[3]);
            }
        }

        int r0 = rbase + rq;
        int r1 = r0 + 8;
#pragma unroll
        for (int nt = 0; nt < 8; nt++) {
            int n = nt * 8 + 2 * (lane & 3);
            float bx = sb2[n], by = sb2[n + 1];
            if (r0 < rows) {
                float2 xv = __half22float2(*(__half2*)(aBuf + rq * LDA + n));
                *(float2*)(out + (size_t)r0 * 64 + n) =
                    make_float2(xv.x + bx + c2[nt][0], xv.y + by + c2[nt][1]);
            }
            if (r1 < rows) {
                float2 xv = __half22float2(*(__half2*)(aBuf + (rq + 8) * LDA + n));
                *(float2*)(out + (size_t)r1 * 64 + n) =
                    make_float2(xv.x + bx + c2[nt][2], xv.y + by + c2[nt][3]);
            }
        }
        __syncwarp();
    }
}

// ---------------- host launcher -------------------------------------------------
extern "C" void kernel_launch(void* const* d_in, const int* in_sizes, int n_in,
                              void* d_out, int out_size) {
    int xAw, xAb, xBw, xBb, xCw, xCb, xDw, xDb, xEw, xEb;
    if (in_sizes[5] == 64) {  // dict order: Aw,Ab,Bw,Bb,Cw,Cb,Dw,Db,Ew,Eb
        xAw = 4; xAb = 5; xBw = 6; xBb = 7; xCw = 8; xCb = 9;
        xDw = 10; xDb = 11; xEw = 12; xEb = 13;
    } else {                  // signature order: Aw,Bw,Cw,Dw,Ew,Ab,Bb,Cb,Db,Eb
        xAw = 4; xBw = 5; xCw = 6; xDw = 7; xEw = 8;
        xAb = 9; xBb = 10; xCb = 11; xDb = 12; xEb = 13;
    }
    const float* h   = (const float*)d_in[0];
    const float* e   = (const float*)d_in[1];
    const int*   src = (const int*)d_in[2];
    const int*   dst = (const int*)d_in[3];
    const float* Aw = (const float*)d_in[xAw]; const float* Ab = (const float*)d_in[xAb];
    const float* Bw = (const float*)d_in[xBw]; const float* Bb = (const float*)d_in[xBb];
    const float* Cw = (const float*)d_in[xCw]; const float* Cb = (const float*)d_in[xCb];
    const float* Dw = (const float*)d_in[xDw]; const float* Db = (const float*)d_in[xDb];
    const float* Ew = (const float*)d_in[xEw]; const float* Eb = (const float*)d_in[xEb];
    const float* g1h = (const float*)d_in[14]; const float* g1e = (const float*)d_in[15];
    const float* g2h = (const float*)d_in[16]; const float* g2e = (const float*)d_in[17];
    const float* b1h = (const float*)d_in[18]; const float* b1e = (const float*)d_in[19];
    const float* b2h = (const float*)d_in[20]; const float* b2e = (const float*)d_in[21];
    const float* Wh1 = (const float*)d_in[22]; const float* bh1 = (const float*)d_in[23];
    const float* Wh2 = (const float*)d_in[24]; const float* bh2 = (const float*)d_in[25];
    const float* We1 = (const float*)d_in[26]; const float* be1 = (const float*)d_in[27];
    const float* We2 = (const float*)d_in[28]; const float* be2 = (const float*)d_in[29];
    float* out = (float*)d_out;

    int N = in_sizes[0] / 64;
    int E = in_sizes[2];
    float invN = 1.0f / (float)N, invE = 1.0f / (float)E;

    cudaFuncSetAttribute(k_node_mma, cudaFuncAttributeMaxDynamicSharedMemorySize, 55296);
    cudaFuncSetAttribute(k_ffn_mma, cudaFuncAttributeMaxDynamicSharedMemorySize, 55552);

    k_zero<<<1, 512>>>();                                                 // 0
    k_stats2<<<2560, 256>>>(h, N, e, E);                                  // 1
    k_node_mma<<<391, 256, 55296>>>(h, Aw, Bw, Cw, Dw, Ab, Bb, Cb, Db,
                                    g1h, b1h, invN, N);                   // 2
    k_edge_mma<<<2960, 128>>>(e, src, dst, Ew, Eb, g1e, b1e, invE, E);    // 3 <- profile
    k_h2s<<<2560, 256>>>(h, N, E);                                        // 4
    k_ffn_mma<<<296, 256, 55552>>>(0, 2, Wh1, bh1, Wh2, bh2, g2h, b2h, invN, N, out);   // 5
    k_ffn_mma<<<296, 256, 55552>>>(1, 3, We1, be1, We2, be2, g2e, b2e, invE, E,
                                   out + (size_t)N * 64);                 // 6
}

// round 14
// speedup vs baseline: 1.0997x; 1.0997x over previous
#include <cuda_runtime.h>
#include <cuda_fp16.h>
#include <cstdint>

#define FULLMASK 0xffffffffu

// Problem sizes (fixed by the dataset)
#define CN 50000
#define CE 800000

// ---------------- scratch (device globals; no cudaMalloc allowed) -------------
__device__ __align__(16) float g_Ah[CN * 64];
__device__ __align__(16) __half g_BCh[CN * 128]; // fp16 interleaved [B0,C0,B1,C1,...]
__device__ __align__(16) __half g_Dh[CN * 64];   // fp16
__device__ __align__(16) float g_h2[CN * 64];
__device__ __align__(16) float g_sx[CN * 128];   // interleaved [ss0,ssh0,ss1,ssh1,...]
__device__ __align__(16) __half g_e2h[CE * 64];  // e after residual, fp16
__device__ float g_stats[4 * 128]; // [set][sum(64) | sumsq(64)]

// ================= mma.sync / ldmatrix helpers (base sm_103 ISA) ===============
__device__ __forceinline__ uint32_t smem_u32(const void* p) {
    return (uint32_t)__cvta_generic_to_shared(p);
}

__device__ __forceinline__ void ldsm_x4(uint32_t (&r)[4], uint32_t addr) {
    asm volatile("ldmatrix.sync.aligned.m8n8.x4.shared.b16 {%0,%1,%2,%3}, [%4];"
                 : "=r"(r[0]), "=r"(r[1]), "=r"(r[2]), "=r"(r[3]) : "r"(addr));
}

// x4 transposed: loads TWO n8k16 B fragments at once.
__device__ __forceinline__ void ldsm_x4t(uint32_t (&b)[4], uint32_t addr) {
    asm volatile("ldmatrix.sync.aligned.m8n8.x4.trans.shared.b16 {%0,%1,%2,%3}, [%4];"
                 : "=r"(b[0]), "=r"(b[1]), "=r"(b[2]), "=r"(b[3]) : "r"(addr));
}

__device__ __forceinline__ void mma_16816(float (&c)[4], const uint32_t (&a)[4],
                                          uint32_t b0, uint32_t b1) {
    asm volatile(
        "mma.sync.aligned.m16n8k16.row.col.f32.f16.f16.f32 "
        "{%0,%1,%2,%3}, {%4,%5,%6,%7}, {%8,%9}, {%0,%1,%2,%3};"
        : "+f"(c[0]), "+f"(c[1]), "+f"(c[2]), "+f"(c[3])
        : "r"(a[0]), "r"(a[1]), "r"(a[2]), "r"(a[3]), "r"(b0), "r"(b1));
}

// helper: compute per-block BN scale/shift into smem (64 threads participate)
__device__ __forceinline__ void bn_fold_smem(int tid, int set,
                                             const float* __restrict__ gamma,
                                             const float* __restrict__ beta,
                                             float inv, float* sc, float* sh) {
    if (tid < 64) {
        float mean = g_stats[set * 128 + tid] * inv;
        float var = g_stats[set * 128 + 64 + tid] * inv - mean * mean;
        float s = gamma[tid] * rsqrtf(var + 1e-5f);
        sc[tid] = s;
        sh[tid] = beta[tid] - mean * s;
    }
}

// ---------------- zero stats accumulators --------------------------------------
__global__ void k_zero() {
    g_stats[threadIdx.x] = 0.f;
}

// ---------------- column mean/var stats for BOTH h and e -----------------------
// blocks [0,512) -> h (set 0); blocks [512, grid) -> e (set 1)
__global__ __launch_bounds__(256) void k_stats2(const float* __restrict__ h, int hrows,
                                                const float* __restrict__ e, int erows) {
    __shared__ float ssum[64], ssq[64];
    int tid = threadIdx.x;
    bool isE = blockIdx.x >= 512;
    const float* __restrict__ x = isE ? e : h;
    int rows = isE ? erows : hrows;
    int set = isE ? 1 : 0;
    int bid = isE ? blockIdx.x - 512 : blockIdx.x;
    int nb = isE ? gridDim.x - 512 : 512;
    if (tid < 64) { ssum[tid] = 0.f; ssq[tid] = 0.f; }
    __syncthreads();
    int cg = tid & 15;
    int r = (bid * 256 + tid) >> 4;
    int rstride = (nb * 256) >> 4;
    float4 s = make_float4(0, 0, 0, 0), q = make_float4(0, 0, 0, 0);
    for (; r < rows; r += rstride) {
        float4 v = *(const float4*)(x + (size_t)r * 64 + cg * 4);
        s.x += v.x; s.y += v.y; s.z += v.z; s.w += v.w;
        q.x += v.x * v.x; q.y += v.y * v.y; q.z += v.z * v.z; q.w += v.w * v.w;
    }
    atomicAdd(&ssum[cg * 4 + 0], s.x); atomicAdd(&ssum[cg * 4 + 1], s.y);
    atomicAdd(&ssum[cg * 4 + 2], s.z); atomicAdd(&ssum[cg * 4 + 3], s.w);
    atomicAdd(&ssq[cg * 4 + 0], q.x);  atomicAdd(&ssq[cg * 4 + 1], q.y);
    atomicAdd(&ssq[cg * 4 + 2], q.z);  atomicAdd(&ssq[cg * 4 + 3], q.w);
    __syncthreads();
    if (tid < 64) {
        atomicAdd(&g_stats[set * 128 + tid], ssum[tid]);
        atomicAdd(&g_stats[set * 128 + 64 + tid], ssq[tid]);
    }
}

// ---------------- node linears via mma ------------------------------------------
// weight slot order in sW cols: [B | C | A | D]. Writes g_BCh (fp16 interleaved),
// g_Dh (fp16), g_Ah (fp32); zeros g_sx for its rows.
__global__ __launch_bounds__(256) void k_node_mma(
    const float* __restrict__ h,
    const float* __restrict__ Aw, const float* __restrict__ Bw,
    const float* __restrict__ Cw, const float* __restrict__ Dw,
    const float* __restrict__ Ab, const float* __restrict__ Bb,
    const float* __restrict__ Cb, const float* __restrict__ Db,
    const float* __restrict__ g1h, const float* __restrict__ b1h,
    float invN, int rows) {
    extern __shared__ char smraw[];
    __half* sW = (__half*)smraw;                         // [64][264]
    __half* sA = (__half*)(smraw + 64 * 264 * 2);        // 8 warps x [16][72]
    float* sc = (float*)(smraw + 64 * 264 * 2 + 8 * 16 * 72 * 2);
    float* sh = sc + 64;
    float* sBias = sh + 64;                              // [4][64] order B,C,A,D
    int tid = threadIdx.x, wid = tid >> 5, lane = tid & 31;

    bn_fold_smem(tid, 0, g1h, b1h, invN, sc, sh);
    __syncthreads();
    for (int i = tid; i < 4 * 4096; i += 256) {
        int m = i >> 12, idx = i & 4095, k = idx >> 6, n = idx & 63;
        const float* W = m == 0 ? Bw : m == 1 ? Cw : m == 2 ? Aw : Dw;
        sW[k * 264 + m * 64 + n] = __float2half(sc[k] * W[idx]);
    }
    {   // bias fold: tid -> (m, n), order B,C,A,D
        int m = tid >> 6, n = tid & 63;
        const float* W = m == 0 ? Bw : m == 1 ? Cw : m == 2 ? Aw : Dw;
        const float* bb = m == 0 ? Bb : m == 1 ? Cb : m == 2 ? Ab : Db;
        float acc = bb[n];
#pragma unroll 8
        for (int k = 0; k < 64; k++) acc += sh[k] * W[k * 64 + n];
        sBias[tid] = acc;
    }
    __syncthreads();

    __half* aBuf = sA + wid * 16 * 72;
    uint32_t aU = smem_u32(aBuf);
    uint32_t wU = smem_u32(sW);
    uint32_t aLd = aU + (uint32_t)(((lane & 15) * 72 + ((lane >> 4) << 3)) * 2);
    uint32_t bRow = lane & 15;
    uint32_t bColOff = (uint32_t)((lane >> 4) << 3);
    int cg = lane & 15, rsub = lane >> 4;
    int ntiles = (rows + 15) >> 4;
    for (int t = blockIdx.x * 8 + wid; t < ntiles; t += gridDim.x * 8) {
        int rbase = t << 4;
#pragma unroll
        for (int j = 0; j < 8; j++) {
            int rloc = rsub + j * 2;
            int row = rbase + rloc; if (row >= rows) row = rows - 1;
            float4 v = *(const float4*)(h + (size_t)row * 64 + cg * 4);
            __half* dp = aBuf + rloc * 72 + cg * 4;
            *(__half2*)dp = __floats2half2_rn(v.x, v.y);
            *(__half2*)(dp + 2) = __floats2half2_rn(v.z, v.w);
        }
        __syncwarp();
        uint32_t afr[4][4];
#pragma unroll
        for (int kt = 0; kt < 4; kt++) ldsm_x4(afr[kt], aLd + kt * 32);
        int r0 = rbase + (lane >> 2), r1 = r0 + 8;
#pragma unroll
        for (int p = 0; p < 2; p++) {
            float c[16][4];
#pragma unroll
            for (int nt = 0; nt < 16; nt++) { c[nt][0] = c[nt][1] = c[nt][2] = c[nt][3] = 0.f; }
#pragma unroll
            for (int ntp = 0; ntp < 8; ntp++) {
#pragma unroll
                for (int kt = 0; kt < 4; kt++) {
                    uint32_t b[4];
                    ldsm_x4t(b, wU + (uint32_t)(((kt * 16 + bRow) * 264 + p * 128 + ntp * 16 + bColOff) * 2));
                    mma_16816(c[2 * ntp],     afr[kt], b[0], b[1]);
                    mma_16816(c[2 * ntp + 1], afr[kt], b[2], b[3]);
                }
            }
            if (p == 0) {
                // B = c[nt], C = c[nt+8] -> fp16 interleaved g_BCh
#pragma unroll
                for (int nt = 0; nt < 8; nt++) {
                    int col = nt * 8 + 2 * (lane & 3);
                    float2 bB = *(const float2*)(sBias + col);
                    float2 bC = *(const float2*)(sBias + 64 + col);
                    if (r0 < rows) {
                        __half2 h0 = __floats2half2_rn(c[nt][0] + bB.x, c[nt + 8][0] + bC.x);
                        __half2 h1 = __floats2half2_rn(c[nt][1] + bB.y, c[nt + 8][1] + bC.y);
                        __half2* dp = (__half2*)(g_BCh + (size_t)r0 * 128 + 2 * col);
                        dp[0] = h0; dp[1] = h1;
                    }
                    if (r1 < rows) {
                        __half2 h0 = __floats2half2_rn(c[nt][2] + bB.x, c[nt + 8][2] + bC.x);
                        __half2 h1 = __floats2half2_rn(c[nt][3] + bB.y, c[nt + 8][3] + bC.y);
                        __half2* dp = (__half2*)(g_BCh + (size_t)r1 * 128 + 2 * col);
                        dp[0] = h0; dp[1] = h1;
                    }
                }
            } else {
                // A = c[0..7] (fp32), D = c[8..15] (fp16)
#pragma unroll
                for (int nt = 0; nt < 8; nt++) {
                    int col = nt * 8 + 2 * (lane & 3);
                    float2 bia = *(const float2*)(sBias + 128 + col);
                    if (r0 < rows)
                        *(float2*)(g_Ah + (size_t)r0 * 64 + col) =
                            make_float2(c[nt][0] + bia.x, c[nt][1] + bia.y);
                    if (r1 < rows)
                        *(float2*)(g_Ah + (size_t)r1 * 64 + col) =
                            make_float2(c[nt][2] + bia.x, c[nt][3] + bia.y);
                }
#pragma unroll
                for (int nt = 8; nt < 16; nt++) {
                    int col = (nt & 7) * 8 + 2 * (lane & 3);
                    float2 bia = *(const float2*)(sBias + 192 + col);
                    if (r0 < rows)
                        *(__half2*)(g_Dh + (size_t)r0 * 64 + col) =
                            __floats2half2_rn(c[nt][0] + bia.x, c[nt][1] + bia.y);
                    if (r1 < rows)
                        *(__half2*)(g_Dh + (size_t)r1 * 64 + col) =
                            __floats2half2_rn(c[nt][2] + bia.x, c[nt][3] + bia.y);
                }
            }
        }
        // zero g_sx for rows r0, r1 (32 float4 per row)
        float4 z4 = make_float4(0.f, 0.f, 0.f, 0.f);
#pragma unroll
        for (int nt = 0; nt < 8; nt++) {
            int off = nt * 16 + (lane & 3) * 4;
            if (r0 < rows) *(float4*)(g_sx + (size_t)r0 * 128 + off) = z4;
            if (r1 < rows) *(float4*)(g_sx + (size_t)r1 * 128 + off) = z4;
        }
        __syncwarp();
    }
}

// ---------------- fused edge kernel: Ee GEMM + gates + segment sums ------------
// 128 threads, 4 CTAs/SM (~121 regs). Weight B fragments HOISTED into registers
// (loop-invariant -> no per-tile ldsm for B). Split-N epilogue; fp16 gathers;
// residual e from the fp16 staged tile; e2 stored fp16; float4 fp32 atomics.
__global__ void __launch_bounds__(128, 4) k_edge_mma(
    const float* __restrict__ e, const int* __restrict__ src, const int* __restrict__ dst,
    const float* __restrict__ Ew, const float* __restrict__ Eb,
    const float* __restrict__ g1e, const float* __restrict__ b1e,
    float invE, int ecount) {
    __shared__ __half sW[64 * 72];
    __shared__ __half sA[4][16 * 72];
    __shared__ float sc[64], sh[64], sb[64];
    int tid = threadIdx.x, wid = tid >> 5, lane = tid & 31;

    bn_fold_smem(tid, 1, g1e, b1e, invE, sc, sh);
    __syncthreads();
    for (int i = tid; i < 4096; i += 128) {
        int k = i >> 6, n = i & 63;
        sW[k * 72 + n] = __float2half(sc[k] * Ew[i]);
    }
    if (tid < 64) {
        float acc = Eb[tid];
#pragma unroll 8
        for (int k = 0; k < 64; k++) acc += sh[k] * Ew[k * 64 + tid];
        sb[tid] = acc;
    }
    __syncthreads();

    uint32_t aU = smem_u32(&sA[wid][0]);
    uint32_t wU = smem_u32(sW);
    uint32_t aLd = aU + (uint32_t)(((lane & 15) * 72 + ((lane >> 4) << 3)) * 2);
    uint32_t bRow = lane & 15;
    uint32_t bColOff = (uint32_t)((lane >> 4) << 3);

    // ---- hoist ALL weight B fragments (loop-invariant) into registers ----
    // bf[nq*4 + kt]: n-16-group nq (0..3), k-16-group kt (0..3)
    uint32_t bf[16][4];
#pragma unroll
    for (int nq = 0; nq < 4; nq++)
#pragma unroll
        for (int kt = 0; kt < 4; kt++)
            ldsm_x4t(bf[nq * 4 + kt],
                     wU + (uint32_t)(((kt * 16 + bRow) * 72 + nq * 16 + bColOff) * 2));

    int cg = lane & 15, rsub = lane >> 4;
    int rq = lane >> 2;  // epilogue local row
    int ntiles = ecount >> 4;
    for (int t = blockIdx.x * 4 + wid; t < ntiles; t += gridDim.x * 4) {
        int ebase = t << 4;
#pragma unroll
        for (int j = 0; j < 8; j++) {
            int rloc = rsub + j * 2;
            float4 v = *(const float4*)(e + (size_t)(ebase + rloc) * 64 + cg * 4);
            __half* dp = &sA[wid][rloc * 72 + cg * 4];
            *(__half2*)dp = __floats2half2_rn(v.x, v.y);
            *(__half2*)(dp + 2) = __floats2half2_rn(v.z, v.w);
        }
        __syncwarp();
        uint32_t afr[4][4];
#pragma unroll
        for (int kt = 0; kt < 4; kt++) ldsm_x4(afr[kt], aLd + kt * 32);
        int r0 = ebase + rq, r1 = r0 + 8;
        int sI0 = src[r0], dI0 = dst[r0], sI1 = src[r1], dI1 = dst[r1];
#pragma unroll
        for (int half = 0; half < 2; half++) {
            float c[4][4];
#pragma unroll
            for (int nt = 0; nt < 4; nt++) { c[nt][0] = c[nt][1] = c[nt][2] = c[nt][3] = 0.f; }
#pragma unroll
            for (int ntp = 0; ntp < 2; ntp++) {
                int nq = half * 2 + ntp;
#pragma unroll
                for (int kt = 0; kt < 4; kt++) {
                    const uint32_t* b = bf[nq * 4 + kt];
                    mma_16816(c[2 * ntp],     afr[kt], b[0], b[1]);
                    mma_16816(c[2 * ntp + 1], afr[kt], b[2], b[3]);
                }
            }
#pragma unroll
            for (int nt = 0; nt < 4; nt++) {
                int c0 = (half * 4 + nt) * 8 + 2 * (lane & 3);
                float2 bia = *(const float2*)(sb + c0);
                // fp16 interleaved gathers: [B0,C0,B1,C1]
                uint2 raw0 = *(const uint2*)(g_BCh + (size_t)sI0 * 128 + 2 * c0);
                uint2 raw1 = *(const uint2*)(g_BCh + (size_t)sI1 * 128 + 2 * c0);
                float2 bc00 = __half22float2(*(__half2*)&raw0.x);  // (B0, C0)
                float2 bc01 = __half22float2(*(__half2*)&raw0.y);  // (B1, C1)
                float2 bc10 = __half22float2(*(__half2*)&raw1.x);
                float2 bc11 = __half22float2(*(__half2*)&raw1.y);
                float2 dh0 = __half22float2(*(const __half2*)(g_Dh + (size_t)dI0 * 64 + c0));
                float2 dh1 = __half22float2(*(const __half2*)(g_Dh + (size_t)dI1 * 64 + c0));
                float en00 = c[nt][0] + bia.x + bc00.y + dh0.x;
                float en01 = c[nt][1] + bia.y + bc01.y + dh0.y;
                float en10 = c[nt][2] + bia.x + bc10.y + dh1.x;
                float en11 = c[nt][3] + bia.y + bc11.y + dh1.y;
                // residual e from the fp16 staged tile (smem)
                float2 ev0 = __half22float2(*(__half2*)(&sA[wid][rq * 72 + c0]));
                float2 ev1 = __half22float2(*(__half2*)(&sA[wid][(rq + 8) * 72 + c0]));
                *(__half2*)(g_e2h + (size_t)r0 * 64 + c0) =
                    __floats2half2_rn(ev0.x + en00, ev0.y + en01);
                *(__half2*)(g_e2h + (size_t)r1 * 64 + c0) =
                    __floats2half2_rn(ev1.x + en10, ev1.y + en11);
                float sg00 = 1.f / (1.f + __expf(-en00));
                float sg01 = 1.f / (1.f + __expf(-en01));
                float sg10 = 1.f / (1.f + __expf(-en10));
                float sg11 = 1.f / (1.f + __expf(-en11));
                atomicAdd((float4*)(g_sx + (size_t)dI0 * 128 + 2 * c0),
                          make_float4(sg00, bc00.x * sg00, sg01, bc01.x * sg01));
                atomicAdd((float4*)(g_sx + (size_t)dI1 * 128 + 2 * c0),
                          make_float4(sg10, bc10.x * sg10, sg11, bc11.x * sg11));
            }
        }
        __syncwarp();
    }
}

// ---------------- h2 = h + Ah + ssh/(ss+eps) + set2 stats; e2 stats (set 3) ----
__global__ __launch_bounds__(256) void k_h2s(const float* __restrict__ h, int hrows, int erows) {
    int tid = threadIdx.x;
    if (blockIdx.x < 512) {
        int lane = tid & 31;
        int warp = (blockIdx.x * 256 + tid) >> 5;
        int nw = (512 * 256) >> 5;
        int c = lane * 2;
        float st_s0 = 0.f, st_s1 = 0.f, st_q0 = 0.f, st_q1 = 0.f;
        for (int r = warp; r < hrows; r += nw) {
            size_t o = (size_t)r * 64 + c;
            float2 hv = *(const float2*)(h + o);
            float2 ah = *(const float2*)(g_Ah + o);
            float4 sx = *(const float4*)(g_sx + (size_t)r * 128 + 2 * c);
            float v0 = hv.x + ah.x + sx.y / (sx.x + 1e-10f);
            float v1 = hv.y + ah.y + sx.w / (sx.z + 1e-10f);
            *(float2*)(g_h2 + o) = make_float2(v0, v1);
            st_s0 += v0; st_q0 += v0 * v0;
            st_s1 += v1; st_q1 += v1 * v1;
        }
        atomicAdd(&g_stats[2 * 128 + c], st_s0);
        atomicAdd(&g_stats[2 * 128 + c + 1], st_s1);
        atomicAdd(&g_stats[2 * 128 + 64 + c], st_q0);
        atomicAdd(&g_stats[2 * 128 + 64 + c + 1], st_q1);
    } else {
        __shared__ float ssum[64], ssq[64];
        if (tid < 64) { ssum[tid] = 0.f; ssq[tid] = 0.f; }
        __syncthreads();
        int bid = blockIdx.x - 512, nb = gridDim.x - 512;
        int cg = tid & 15;
        int r = (bid * 256 + tid) >> 4;
        int rstride = (nb * 256) >> 4;
        float4 s = make_float4(0, 0, 0, 0), q = make_float4(0, 0, 0, 0);
        for (; r < erows; r += rstride) {
            uint2 raw = *(const uint2*)(g_e2h + (size_t)r * 64 + cg * 4);
            float2 f01 = __half22float2(*(__half2*)&raw.x);
            float2 f23 = __half22float2(*(__half2*)&raw.y);
            s.x += f01.x; s.y += f01.y; s.z += f23.x; s.w += f23.y;
            q.x += f01.x * f01.x; q.y += f01.y * f01.y;
            q.z += f23.x * f23.x; q.w += f23.y * f23.y;
        }
        atomicAdd(&ssum[cg * 4 + 0], s.x); atomicAdd(&ssum[cg * 4 + 1], s.y);
        atomicAdd(&ssum[cg * 4 + 2], s.z); atomicAdd(&ssum[cg * 4 + 3], s.w);
        atomicAdd(&ssq[cg * 4 + 0], q.x);  atomicAdd(&ssq[cg * 4 + 1], q.y);
        atomicAdd(&ssq[cg * 4 + 2], q.z);  atomicAdd(&ssq[cg * 4 + 3], q.w);
        __syncthreads();
        if (tid < 64) {
            atomicAdd(&g_stats[3 * 128 + tid], ssum[tid]);
            atomicAdd(&g_stats[3 * 128 + 64 + tid], ssq[tid]);
        }
    }
}

// ---------------- FFN via mma.sync: out = x2 + relu(bn(x2)@W1+b1)@W2 + b2 ------
// 256 threads (8 warps), dynamic smem, 2 CTAs/SM. Residual from staged fp16.
// which==0: source g_h2 (fp32); which==1: source g_e2h (fp16 direct copy).
__global__ void __launch_bounds__(256) k_ffn_mma(
    int which,
    int set,    // 2 (h) or 3 (e)
    const float* __restrict__ W1, const float* __restrict__ b1,
    const float* __restrict__ W2, const float* __restrict__ b2,
    const float* __restrict__ gamma, const float* __restrict__ beta,
    float inv, int rows, float* __restrict__ out) {
    const int LDA = 72, LDB1 = 136, LDB2 = 72;
    extern __shared__ char smraw[];
    __half* sB1 = (__half*)smraw;                       // 17408 B
    __half* sB2 = (__half*)(smraw + 17408);             // 18432 B
    __half* sA  = (__half*)(smraw + 35840);             // 8 x [16*72] = 18432 B
    float* sb1 = (float*)(smraw + 54272);               // 512 B
    float* sb2 = (float*)(smraw + 54784);               // 256 B
    float* sc  = (float*)(smraw + 55040);               // 256 B
    float* sh  = (float*)(smraw + 55296);               // 256 B

    int tid = threadIdx.x, wid = tid >> 5, lane = tid & 31;
    bn_fold_smem(tid, set, gamma, beta, inv, sc, sh);
    __syncthreads();
    for (int i = tid; i < 64 * 128; i += 256) {
        int k = i >> 7, n = i & 127;
        sB1[k * LDB1 + n] = __float2half(sc[k] * W1[i]);
    }
    for (int i = tid; i < 128 * 64; i += 256) {
        int k = i >> 6, n = i & 63;
        sB2[k * LDB2 + n] = __float2half(W2[i]);
    }
    if (tid < 128) {   // bias1 fold
        float acc = b1[tid];
#pragma unroll 8
        for (int k = 0; k < 64; k++) acc += sh[k] * W1[k * 128 + tid];
        sb1[tid] = acc;
    }
    if (tid < 64) sb2[tid] = b2[tid];
    __syncthreads();

    __half* aBuf = sA + wid * 16 * 72;
    uint32_t aU = smem_u32(aBuf);
    uint32_t b1U = smem_u32(sB1);
    uint32_t b2U = smem_u32(sB2);
    int cg = lane & 15;
    uint32_t aLdAddr = aU + (uint32_t)(((lane & 15) * LDA + ((lane >> 4) << 3)) * 2);
    uint32_t bRow = (uint32_t)(lane & 15);
    uint32_t bColOff = (uint32_t)((lane >> 4) << 3);
    int rq = lane >> 2;

    int ngroups = (rows + 15) >> 4;
    int gw = blockIdx.x * 8 + wid;
    int gstride = gridDim.x * 8;
    for (int g = gw; g < ngroups; g += gstride) {
        int rbase = g << 4;
        int rsub = lane >> 4;
        if (which == 0) {
#pragma unroll
            for (int j = 0; j < 8; j++) {
                int rloc = rsub + j * 2;
                int row = rbase + rloc; if (row >= rows) row = rows - 1;
                float4 v = *(const float4*)(g_h2 + (size_t)row * 64 + cg * 4);
                __half* dstp = aBuf + rloc * LDA + cg * 4;
                *(__half2*)(dstp) = __floats2half2_rn(v.x, v.y);
                *(__half2*)(dstp + 2) = __floats2half2_rn(v.z, v.w);
            }
        } else {
#pragma unroll
            for (int j = 0; j < 8; j++) {
                int rloc = rsub + j * 2;
                int row = rbase + rloc; if (row >= rows) row = rows - 1;
                uint2 v = *(const uint2*)(g_e2h + (size_t)row * 64 + cg * 4);
                *(uint2*)(aBuf + rloc * LDA + cg * 4) = v;
            }
        }
        __syncwarp();

        uint32_t afr[4][4];
#pragma unroll
        for (int kt = 0; kt < 4; kt++)
            ldsm_x4(afr[kt], aLdAddr + (uint32_t)(kt * 16 * 2));

        float c1[16][4];
#pragma unroll
        for (int nt = 0; nt < 16; nt++) { c1[nt][0] = c1[nt][1] = c1[nt][2] = c1[nt][3] = 0.f; }
#pragma unroll
        for (int ntp = 0; ntp < 8; ntp++) {
#pragma unroll
            for (int kt = 0; kt < 4; kt++) {
                uint32_t b[4];
                ldsm_x4t(b, b1U + (uint32_t)((((kt * 16) + bRow) * LDB1 + ntp * 16 + bColOff) * 2));
                mma_16816(c1[2 * ntp],     afr[kt], b[0], b[1]);
                mma_16816(c1[2 * ntp + 1], afr[kt], b[2], b[3]);
            }
        }

        uint32_t a2[8][4];
#pragma unroll
        for (int nt = 0; nt < 16; nt++) {
            int n0 = nt * 8 + 2 * (lane & 3);
            float bx = sb1[n0], by = sb1[n0 + 1];
            __half2 lo = __floats2half2_rn(fmaxf(c1[nt][0] + bx, 0.f),
                                           fmaxf(c1[nt][1] + by, 0.f));
            __half2 hi = __floats2half2_rn(fmaxf(c1[nt][2] + bx, 0.f),
                                           fmaxf(c1[nt][3] + by, 0.f));
            int kt2 = nt >> 1, base = (nt & 1) * 2;
            a2[kt2][base]     = *reinterpret_cast<uint32_t*>(&lo);
            a2[kt2][base + 1] = *reinterpret_cast<uint32_t*>(&hi);
        }

        float c2[8][4];
#pragma unroll
        for (int nt = 0; nt < 8; nt++) { c2[nt][0] = c2[nt][1] = c2[nt][2] = c2[nt][3] = 0.f; }
#pragma unroll
        for (int ntp = 0; ntp < 4; ntp++) {
#pragma unroll
            for (int kt = 0; kt < 8; kt++) {
                uint32_t b[4];
                ldsm_x4t(b, b2U + (uint32_t)((((kt * 16) + bRow) * LDB2 + ntp * 16 + bColOff) * 2));
                mma_16816(c2[2 * ntp],     a2[kt], b[0], b[1]);
                mma_16816(c2[2 * ntp + 1], a2[kt], b[2], b[3]);
            }
        }

        int r0 = rbase + rq;
        int r1 = r0 + 8;
#pragma unroll
        for (int nt = 0; nt < 8; nt++) {
            int n = nt * 8 + 2 * (lane & 3);
            float bx = sb2[n], by = sb2[n + 1];
            if (r0 < rows) {
                float2 xv = __half22float2(*(__half2*)(aBuf + rq * LDA + n));
                *(float2*)(out + (size_t)r0 * 64 + n) =
                    make_float2(xv.x + bx + c2[nt][0], xv.y + by + c2[nt][1]);
            }
            if (r1 < rows) {
                float2 xv = __half22float2(*(__half2*)(aBuf + (rq + 8) * LDA + n));
                *(float2*)(out + (size_t)r1 * 64 + n) =
                    make_float2(xv.x + bx + c2[nt][2], xv.y + by + c2[nt][3]);
            }
        }
        __syncwarp();
    }
}

// ---------------- host launcher -------------------------------------------------
extern "C" void kernel_launch(void* const* d_in, const int* in_sizes, int n_in,
                              void* d_out, int out_size) {
    int xAw, xAb, xBw, xBb, xCw, xCb, xDw, xDb, xEw, xEb;
    if (in_sizes[5] == 64) {  // dict order: Aw,Ab,Bw,Bb,Cw,Cb,Dw,Db,Ew,Eb
        xAw = 4; xAb = 5; xBw = 6; xBb = 7; xCw = 8; xCb = 9;
        xDw = 10; xDb = 11; xEw = 12; xEb = 13;
    } else {                  // signature order: Aw,Bw,Cw,Dw,Ew,Ab,Bb,Cb,Db,Eb
        xAw = 4; xBw = 5; xCw = 6; xDw = 7; xEw = 8;
        xAb = 9; xBb = 10; xCb = 11; xDb = 12; xEb = 13;
    }
    const float* h   = (const float*)d_in[0];
    const float* e   = (const float*)d_in[1];
    const int*   src = (const int*)d_in[2];
    const int*   dst = (const int*)d_in[3];
    const float* Aw = (const float*)d_in[xAw]; const float* Ab = (const float*)d_in[xAb];
    const float* Bw = (const float*)d_in[xBw]; const float* Bb = (const float*)d_in[xBb];
    const float* Cw = (const float*)d_in[xCw]; const float* Cb = (const float*)d_in[xCb];
    const float* Dw = (const float*)d_in[xDw]; const float* Db = (const float*)d_in[xDb];
    const float* Ew = (const float*)d_in[xEw]; const float* Eb = (const float*)d_in[xEb];
    const float* g1h = (const float*)d_in[14]; const float* g1e = (const float*)d_in[15];
    const float* g2h = (const float*)d_in[16]; const float* g2e = (const float*)d_in[17];
    const float* b1h = (const float*)d_in[18]; const float* b1e = (const float*)d_in[19];
    const float* b2h = (const float*)d_in[20]; const float* b2e = (const float*)d_in[21];
    const float* Wh1 = (const float*)d_in[22]; const float* bh1 = (const float*)d_in[23];
    const float* Wh2 = (const float*)d_in[24]; const float* bh2 = (const float*)d_in[25];
    const float* We1 = (const float*)d_in[26]; const float* be1 = (const float*)d_in[27];
    const float* We2 = (const float*)d_in[28]; const float* be2 = (const float*)d_in[29];
    float* out = (float*)d_out;

    int N = in_sizes[0] / 64;
    int E = in_sizes[2];
    float invN = 1.0f / (float)N, invE = 1.0f / (float)E;

    cudaFuncSetAttribute(k_node_mma, cudaFuncAttributeMaxDynamicSharedMemorySize, 55296);
    cudaFuncSetAttribute(k_ffn_mma, cudaFuncAttributeMaxDynamicSharedMemorySize, 55552);

    k_zero<<<1, 512>>>();                                                 // 0
    k_stats2<<<2560, 256>>>(h, N, e, E);                                  // 1
    k_node_mma<<<391, 256, 55296>>>(h, Aw, Bw, Cw, Dw, Ab, Bb, Cb, Db,
                                    g1h, b1h, invN, N);                   // 2
    k_edge_mma<<<2960, 128>>>(e, src, dst, Ew, Eb, g1e, b1e, invE, E);    // 3 <- profile
    k_h2s<<<2560, 256>>>(h, N, E);                                        // 4
    k_ffn_mma<<<296, 256, 55552>>>(0, 2, Wh1, bh1, Wh2, bh2, g2h, b2h, invN, N, out);   // 5
    k_ffn_mma<<<296, 256, 55552>>>(1, 3, We1, be1, We2, be2, g2e, b2e, invE, E,
                                   out + (size_t)N * 64);                 // 6
}

// round 15
// speedup vs baseline: 1.1187x; 1.0172x over previous
#include <cuda_runtime.h>
#include <cuda_fp16.h>
#include <cstdint>

#define FULLMASK 0xffffffffu

// Problem sizes (fixed by the dataset)
#define CN 50000
#define CE 800000

// ---------------- scratch (device globals; no cudaMalloc allowed) -------------
__device__ __align__(16) float g_Ah[CN * 64];
__device__ __align__(16) __half g_BCh[CN * 128]; // fp16 interleaved [B0,C0,B1,C1,...]
__device__ __align__(16) __half g_Dh[CN * 64];   // fp16
__device__ __align__(16) float g_h2[CN * 64];
__device__ __align__(16) float g_sx[CN * 128];   // interleaved [ss0,ssh0,ss1,ssh1,...]
__device__ __align__(16) __half g_e2h[CE * 64];  // e after residual, fp16
__device__ float g_stats[4 * 128]; // [set][sum(64) | sumsq(64)]

// ================= mma.sync / ldmatrix helpers (base sm_103 ISA) ===============
__device__ __forceinline__ uint32_t smem_u32(const void* p) {
    return (uint32_t)__cvta_generic_to_shared(p);
}

__device__ __forceinline__ void ldsm_x4(uint32_t (&r)[4], uint32_t addr) {
    asm volatile("ldmatrix.sync.aligned.m8n8.x4.shared.b16 {%0,%1,%2,%3}, [%4];"
                 : "=r"(r[0]), "=r"(r[1]), "=r"(r[2]), "=r"(r[3]) : "r"(addr));
}

// x4 transposed: loads TWO n8k16 B fragments at once.
__device__ __forceinline__ void ldsm_x4t(uint32_t (&b)[4], uint32_t addr) {
    asm volatile("ldmatrix.sync.aligned.m8n8.x4.trans.shared.b16 {%0,%1,%2,%3}, [%4];"
                 : "=r"(b[0]), "=r"(b[1]), "=r"(b[2]), "=r"(b[3]) : "r"(addr));
}

__device__ __forceinline__ void mma_16816(float (&c)[4], const uint32_t (&a)[4],
                                          uint32_t b0, uint32_t b1) {
    asm volatile(
        "mma.sync.aligned.m16n8k16.row.col.f32.f16.f16.f32 "
        "{%0,%1,%2,%3}, {%4,%5,%6,%7}, {%8,%9}, {%0,%1,%2,%3};"
        : "+f"(c[0]), "+f"(c[1]), "+f"(c[2]), "+f"(c[3])
        : "r"(a[0]), "r"(a[1]), "r"(a[2]), "r"(a[3]), "r"(b0), "r"(b1));
}

// helper: compute per-block BN scale/shift into smem (64 threads participate)
__device__ __forceinline__ void bn_fold_smem(int tid, int set,
                                             const float* __restrict__ gamma,
                                             const float* __restrict__ beta,
                                             float inv, float* sc, float* sh) {
    if (tid < 64) {
        float mean = g_stats[set * 128 + tid] * inv;
        float var = g_stats[set * 128 + 64 + tid] * inv - mean * mean;
        float s = gamma[tid] * rsqrtf(var + 1e-5f);
        sc[tid] = s;
        sh[tid] = beta[tid] - mean * s;
    }
}

// ---------------- zero stats accumulators --------------------------------------
__global__ void k_zero() {
    g_stats[threadIdx.x] = 0.f;
}

// ---------------- column mean/var stats for BOTH h and e -----------------------
// blocks [0,512) -> h (set 0); blocks [512, grid) -> e (set 1)
__global__ __launch_bounds__(256) void k_stats2(const float* __restrict__ h, int hrows,
                                                const float* __restrict__ e, int erows) {
    __shared__ float ssum[64], ssq[64];
    int tid = threadIdx.x;
    bool isE = blockIdx.x >= 512;
    const float* __restrict__ x = isE ? e : h;
    int rows = isE ? erows : hrows;
    int set = isE ? 1 : 0;
    int bid = isE ? blockIdx.x - 512 : blockIdx.x;
    int nb = isE ? gridDim.x - 512 : 512;
    if (tid < 64) { ssum[tid] = 0.f; ssq[tid] = 0.f; }
    __syncthreads();
    int cg = tid & 15;
    int r = (bid * 256 + tid) >> 4;
    int rstride = (nb * 256) >> 4;
    float4 s = make_float4(0, 0, 0, 0), q = make_float4(0, 0, 0, 0);
    for (; r < rows; r += rstride) {
        float4 v = *(const float4*)(x + (size_t)r * 64 + cg * 4);
        s.x += v.x; s.y += v.y; s.z += v.z; s.w += v.w;
        q.x += v.x * v.x; q.y += v.y * v.y; q.z += v.z * v.z; q.w += v.w * v.w;
    }
    atomicAdd(&ssum[cg * 4 + 0], s.x); atomicAdd(&ssum[cg * 4 + 1], s.y);
    atomicAdd(&ssum[cg * 4 + 2], s.z); atomicAdd(&ssum[cg * 4 + 3], s.w);
    atomicAdd(&ssq[cg * 4 + 0], q.x);  atomicAdd(&ssq[cg * 4 + 1], q.y);
    atomicAdd(&ssq[cg * 4 + 2], q.z);  atomicAdd(&ssq[cg * 4 + 3], q.w);
    __syncthreads();
    if (tid < 64) {
        atomicAdd(&g_stats[set * 128 + tid], ssum[tid]);
        atomicAdd(&g_stats[set * 128 + 64 + tid], ssq[tid]);
    }
}

// ---------------- node linears via mma ------------------------------------------
// weight slot order in sW cols: [B | C | A | D]. Writes g_BCh (fp16 interleaved),
// g_Dh (fp16), g_Ah (fp32); zeros g_sx for its rows.
__global__ __launch_bounds__(256) void k_node_mma(
    const float* __restrict__ h,
    const float* __restrict__ Aw, const float* __restrict__ Bw,
    const float* __restrict__ Cw, const float* __restrict__ Dw,
    const float* __restrict__ Ab, const float* __restrict__ Bb,
    const float* __restrict__ Cb, const float* __restrict__ Db,
    const float* __restrict__ g1h, const float* __restrict__ b1h,
    float invN, int rows) {
    extern __shared__ char smraw[];
    __half* sW = (__half*)smraw;                         // [64][264]
    __half* sA = (__half*)(smraw + 64 * 264 * 2);        // 8 warps x [16][72]
    float* sc = (float*)(smraw + 64 * 264 * 2 + 8 * 16 * 72 * 2);
    float* sh = sc + 64;
    float* sBias = sh + 64;                              // [4][64] order B,C,A,D
    int tid = threadIdx.x, wid = tid >> 5, lane = tid & 31;

    bn_fold_smem(tid, 0, g1h, b1h, invN, sc, sh);
    __syncthreads();
    for (int i = tid; i < 4 * 4096; i += 256) {
        int m = i >> 12, idx = i & 4095, k = idx >> 6, n = idx & 63;
        const float* W = m == 0 ? Bw : m == 1 ? Cw : m == 2 ? Aw : Dw;
        sW[k * 264 + m * 64 + n] = __float2half(sc[k] * W[idx]);
    }
    {   // bias fold: tid -> (m, n), order B,C,A,D
        int m = tid >> 6, n = tid & 63;
        const float* W = m == 0 ? Bw : m == 1 ? Cw : m == 2 ? Aw : Dw;
        const float* bb = m == 0 ? Bb : m == 1 ? Cb : m == 2 ? Ab : Db;
        float acc = bb[n];
#pragma unroll 8
        for (int k = 0; k < 64; k++) acc += sh[k] * W[k * 64 + n];
        sBias[tid] = acc;
    }
    __syncthreads();

    __half* aBuf = sA + wid * 16 * 72;
    uint32_t aU = smem_u32(aBuf);
    uint32_t wU = smem_u32(sW);
    uint32_t aLd = aU + (uint32_t)(((lane & 15) * 72 + ((lane >> 4) << 3)) * 2);
    uint32_t bRow = lane & 15;
    uint32_t bColOff = (uint32_t)((lane >> 4) << 3);
    int cg = lane & 15, rsub = lane >> 4;
    int ntiles = (rows + 15) >> 4;
    for (int t = blockIdx.x * 8 + wid; t < ntiles; t += gridDim.x * 8) {
        int rbase = t << 4;
#pragma unroll
        for (int j = 0; j < 8; j++) {
            int rloc = rsub + j * 2;
            int row = rbase + rloc; if (row >= rows) row = rows - 1;
            float4 v = *(const float4*)(h + (size_t)row * 64 + cg * 4);
            __half* dp = aBuf + rloc * 72 + cg * 4;
            *(__half2*)dp = __floats2half2_rn(v.x, v.y);
            *(__half2*)(dp + 2) = __floats2half2_rn(v.z, v.w);
        }
        __syncwarp();
        uint32_t afr[4][4];
#pragma unroll
        for (int kt = 0; kt < 4; kt++) ldsm_x4(afr[kt], aLd + kt * 32);
        int r0 = rbase + (lane >> 2), r1 = r0 + 8;
#pragma unroll
        for (int p = 0; p < 2; p++) {
            float c[16][4];
#pragma unroll
            for (int nt = 0; nt < 16; nt++) { c[nt][0] = c[nt][1] = c[nt][2] = c[nt][3] = 0.f; }
#pragma unroll
            for (int ntp = 0; ntp < 8; ntp++) {
#pragma unroll
                for (int kt = 0; kt < 4; kt++) {
                    uint32_t b[4];
                    ldsm_x4t(b, wU + (uint32_t)(((kt * 16 + bRow) * 264 + p * 128 + ntp * 16 + bColOff) * 2));
                    mma_16816(c[2 * ntp],     afr[kt], b[0], b[1]);
                    mma_16816(c[2 * ntp + 1], afr[kt], b[2], b[3]);
                }
            }
            if (p == 0) {
                // B = c[nt], C = c[nt+8] -> fp16 interleaved g_BCh
#pragma unroll
                for (int nt = 0; nt < 8; nt++) {
                    int col = nt * 8 + 2 * (lane & 3);
                    float2 bB = *(const float2*)(sBias + col);
                    float2 bC = *(const float2*)(sBias + 64 + col);
                    if (r0 < rows) {
                        __half2 h0 = __floats2half2_rn(c[nt][0] + bB.x, c[nt + 8][0] + bC.x);
                        __half2 h1 = __floats2half2_rn(c[nt][1] + bB.y, c[nt + 8][1] + bC.y);
                        __half2* dp = (__half2*)(g_BCh + (size_t)r0 * 128 + 2 * col);
                        dp[0] = h0; dp[1] = h1;
                    }
                    if (r1 < rows) {
                        __half2 h0 = __floats2half2_rn(c[nt][2] + bB.x, c[nt + 8][2] + bC.x);
                        __half2 h1 = __floats2half2_rn(c[nt][3] + bB.y, c[nt + 8][3] + bC.y);
                        __half2* dp = (__half2*)(g_BCh + (size_t)r1 * 128 + 2 * col);
                        dp[0] = h0; dp[1] = h1;
                    }
                }
            } else {
                // A = c[0..7] (fp32), D = c[8..15] (fp16)
#pragma unroll
                for (int nt = 0; nt < 8; nt++) {
                    int col = nt * 8 + 2 * (lane & 3);
                    float2 bia = *(const float2*)(sBias + 128 + col);
                    if (r0 < rows)
                        *(float2*)(g_Ah + (size_t)r0 * 64 + col) =
                            make_float2(c[nt][0] + bia.x, c[nt][1] + bia.y);
                    if (r1 < rows)
                        *(float2*)(g_Ah + (size_t)r1 * 64 + col) =
                            make_float2(c[nt][2] + bia.x, c[nt][3] + bia.y);
                }
#pragma unroll
                for (int nt = 8; nt < 16; nt++) {
                    int col = (nt & 7) * 8 + 2 * (lane & 3);
                    float2 bia = *(const float2*)(sBias + 192 + col);
                    if (r0 < rows)
                        *(__half2*)(g_Dh + (size_t)r0 * 64 + col) =
                            __floats2half2_rn(c[nt][0] + bia.x, c[nt][1] + bia.y);
                    if (r1 < rows)
                        *(__half2*)(g_Dh + (size_t)r1 * 64 + col) =
                            __floats2half2_rn(c[nt][2] + bia.x, c[nt][3] + bia.y);
                }
            }
        }
        // zero g_sx for rows r0, r1 (32 float4 per row)
        float4 z4 = make_float4(0.f, 0.f, 0.f, 0.f);
#pragma unroll
        for (int nt = 0; nt < 8; nt++) {
            int off = nt * 16 + (lane & 3) * 4;
            if (r0 < rows) *(float4*)(g_sx + (size_t)r0 * 128 + off) = z4;
            if (r1 < rows) *(float4*)(g_sx + (size_t)r1 * 128 + off) = z4;
        }
        __syncwarp();
    }
}

// ---------------- fused edge kernel: Ee GEMM + gates + segment sums ------------
// 128 threads, 5 CTAs/SM (~96 regs). HYBRID hoist: B fragments for n-groups 0-1
// live in registers; n-groups 2-3 ldsm'd per tile. Split-N epilogue; fp16
// gathers; residual e from the fp16 staged tile; e2 fp16; float4 atomics.
__global__ void __launch_bounds__(128, 5) k_edge_mma(
    const float* __restrict__ e, const int* __restrict__ src, const int* __restrict__ dst,
    const float* __restrict__ Ew, const float* __restrict__ Eb,
    const float* __restrict__ g1e, const float* __restrict__ b1e,
    float invE, int ecount) {
    __shared__ __half sW[64 * 72];
    __shared__ __half sA[4][16 * 72];
    __shared__ float sc[64], sh[64], sb[64];
    int tid = threadIdx.x, wid = tid >> 5, lane = tid & 31;

    bn_fold_smem(tid, 1, g1e, b1e, invE, sc, sh);
    __syncthreads();
    for (int i = tid; i < 4096; i += 128) {
        int k = i >> 6, n = i & 63;
        sW[k * 72 + n] = __float2half(sc[k] * Ew[i]);
    }
    if (tid < 64) {
        float acc = Eb[tid];
#pragma unroll 8
        for (int k = 0; k < 64; k++) acc += sh[k] * Ew[k * 64 + tid];
        sb[tid] = acc;
    }
    __syncthreads();

    uint32_t aU = smem_u32(&sA[wid][0]);
    uint32_t wU = smem_u32(sW);
    uint32_t aLd = aU + (uint32_t)(((lane & 15) * 72 + ((lane >> 4) << 3)) * 2);
    uint32_t bRow = lane & 15;
    uint32_t bColOff = (uint32_t)((lane >> 4) << 3);

    // ---- hoist B fragments for n-groups 0-1 into registers (8 frags, 32 regs) --
    uint32_t bf[8][4];
#pragma unroll
    for (int nq = 0; nq < 2; nq++)
#pragma unroll
        for (int kt = 0; kt < 4; kt++)
            ldsm_x4t(bf[nq * 4 + kt],
                     wU + (uint32_t)(((kt * 16 + bRow) * 72 + nq * 16 + bColOff) * 2));

    int cg = lane & 15, rsub = lane >> 4;
    int rq = lane >> 2;  // epilogue local row
    int ntiles = ecount >> 4;
    for (int t = blockIdx.x * 4 + wid; t < ntiles; t += gridDim.x * 4) {
        int ebase = t << 4;
#pragma unroll
        for (int j = 0; j < 8; j++) {
            int rloc = rsub + j * 2;
            float4 v = *(const float4*)(e + (size_t)(ebase + rloc) * 64 + cg * 4);
            __half* dp = &sA[wid][rloc * 72 + cg * 4];
            *(__half2*)dp = __floats2half2_rn(v.x, v.y);
            *(__half2*)(dp + 2) = __floats2half2_rn(v.z, v.w);
        }
        __syncwarp();
        uint32_t afr[4][4];
#pragma unroll
        for (int kt = 0; kt < 4; kt++) ldsm_x4(afr[kt], aLd + kt * 32);
        int r0 = ebase + rq, r1 = r0 + 8;
        int sI0 = src[r0], dI0 = dst[r0], sI1 = src[r1], dI1 = dst[r1];
#pragma unroll
        for (int half = 0; half < 2; half++) {
            float c[4][4];
#pragma unroll
            for (int nt = 0; nt < 4; nt++) { c[nt][0] = c[nt][1] = c[nt][2] = c[nt][3] = 0.f; }
#pragma unroll
            for (int ntp = 0; ntp < 2; ntp++) {
                int nq = half * 2 + ntp;
                if (half == 0) {
#pragma unroll
                    for (int kt = 0; kt < 4; kt++) {
                        const uint32_t* b = bf[nq * 4 + kt];
                        mma_16816(c[2 * ntp],     afr[kt], b[0], b[1]);
                        mma_16816(c[2 * ntp + 1], afr[kt], b[2], b[3]);
                    }
                } else {
#pragma unroll
                    for (int kt = 0; kt < 4; kt++) {
                        uint32_t b[4];
                        ldsm_x4t(b, wU + (uint32_t)(((kt * 16 + bRow) * 72 + nq * 16 + bColOff) * 2));
                        mma_16816(c[2 * ntp],     afr[kt], b[0], b[1]);
                        mma_16816(c[2 * ntp + 1], afr[kt], b[2], b[3]);
                    }
                }
            }
#pragma unroll
            for (int nt = 0; nt < 4; nt++) {
                int c0 = (half * 4 + nt) * 8 + 2 * (lane & 3);
                float2 bia = *(const float2*)(sb + c0);
                // fp16 interleaved gathers: [B0,C0,B1,C1]
                uint2 raw0 = *(const uint2*)(g_BCh + (size_t)sI0 * 128 + 2 * c0);
                uint2 raw1 = *(const uint2*)(g_BCh + (size_t)sI1 * 128 + 2 * c0);
                float2 bc00 = __half22float2(*(__half2*)&raw0.x);  // (B0, C0)
                float2 bc01 = __half22float2(*(__half2*)&raw0.y);  // (B1, C1)
                float2 bc10 = __half22float2(*(__half2*)&raw1.x);
                float2 bc11 = __half22float2(*(__half2*)&raw1.y);
                float2 dh0 = __half22float2(*(const __half2*)(g_Dh + (size_t)dI0 * 64 + c0));
                float2 dh1 = __half22float2(*(const __half2*)(g_Dh + (size_t)dI1 * 64 + c0));
                float en00 = c[nt][0] + bia.x + bc00.y + dh0.x;
                float en01 = c[nt][1] + bia.y + bc01.y + dh0.y;
                float en10 = c[nt][2] + bia.x + bc10.y + dh1.x;
                float en11 = c[nt][3] + bia.y + bc11.y + dh1.y;
                // residual e from the fp16 staged tile (smem)
                float2 ev0 = __half22float2(*(__half2*)(&sA[wid][rq * 72 + c0]));
                float2 ev1 = __half22float2(*(__half2*)(&sA[wid][(rq + 8) * 72 + c0]));
                *(__half2*)(g_e2h + (size_t)r0 * 64 + c0) =
                    __floats2half2_rn(ev0.x + en00, ev0.y + en01);
                *(__half2*)(g_e2h + (size_t)r1 * 64 + c0) =
                    __floats2half2_rn(ev1.x + en10, ev1.y + en11);
                float sg00 = 1.f / (1.f + __expf(-en00));
                float sg01 = 1.f / (1.f + __expf(-en01));
                float sg10 = 1.f / (1.f + __expf(-en10));
                float sg11 = 1.f / (1.f + __expf(-en11));
                atomicAdd((float4*)(g_sx + (size_t)dI0 * 128 + 2 * c0),
                          make_float4(sg00, bc00.x * sg00, sg01, bc01.x * sg01));
                atomicAdd((float4*)(g_sx + (size_t)dI1 * 128 + 2 * c0),
                          make_float4(sg10, bc10.x * sg10, sg11, bc11.x * sg11));
            }
        }
        __syncwarp();
    }
}

// ---------------- h2 = h + Ah + ssh/(ss+eps) + set2 stats; e2 stats (set 3) ----
__global__ __launch_bounds__(256) void k_h2s(const float* __restrict__ h, int hrows, int erows) {
    int tid = threadIdx.x;
    if (blockIdx.x < 512) {
        int lane = tid & 31;
        int warp = (blockIdx.x * 256 + tid) >> 5;
        int nw = (512 * 256) >> 5;
        int c = lane * 2;
        float st_s0 = 0.f, st_s1 = 0.f, st_q0 = 0.f, st_q1 = 0.f;
        for (int r = warp; r < hrows; r += nw) {
            size_t o = (size_t)r * 64 + c;
            float2 hv = *(const float2*)(h + o);
            float2 ah = *(const float2*)(g_Ah + o);
            float4 sx = *(const float4*)(g_sx + (size_t)r * 128 + 2 * c);
            float v0 = hv.x + ah.x + sx.y / (sx.x + 1e-10f);
            float v1 = hv.y + ah.y + sx.w / (sx.z + 1e-10f);
            *(float2*)(g_h2 + o) = make_float2(v0, v1);
            st_s0 += v0; st_q0 += v0 * v0;
            st_s1 += v1; st_q1 += v1 * v1;
        }
        atomicAdd(&g_stats[2 * 128 + c], st_s0);
        atomicAdd(&g_stats[2 * 128 + c + 1], st_s1);
        atomicAdd(&g_stats[2 * 128 + 64 + c], st_q0);
        atomicAdd(&g_stats[2 * 128 + 64 + c + 1], st_q1);
    } else {
        __shared__ float ssum[64], ssq[64];
        if (tid < 64) { ssum[tid] = 0.f; ssq[tid] = 0.f; }
        __syncthreads();
        int bid = blockIdx.x - 512, nb = gridDim.x - 512;
        int cg = tid & 15;
        int r = (bid * 256 + tid) >> 4;
        int rstride = (nb * 256) >> 4;
        float4 s = make_float4(0, 0, 0, 0), q = make_float4(0, 0, 0, 0);
        for (; r < erows; r += rstride) {
            uint2 raw = *(const uint2*)(g_e2h + (size_t)r * 64 + cg * 4);
            float2 f01 = __half22float2(*(__half2*)&raw.x);
            float2 f23 = __half22float2(*(__half2*)&raw.y);
            s.x += f01.x; s.y += f01.y; s.z += f23.x; s.w += f23.y;
            q.x += f01.x * f01.x; q.y += f01.y * f01.y;
            q.z += f23.x * f23.x; q.w += f23.y * f23.y;
        }
        atomicAdd(&ssum[cg * 4 + 0], s.x); atomicAdd(&ssum[cg * 4 + 1], s.y);
        atomicAdd(&ssum[cg * 4 + 2], s.z); atomicAdd(&ssum[cg * 4 + 3], s.w);
        atomicAdd(&ssq[cg * 4 + 0], q.x);  atomicAdd(&ssq[cg * 4 + 1], q.y);
        atomicAdd(&ssq[cg * 4 + 2], q.z);  atomicAdd(&ssq[cg * 4 + 3], q.w);
        __syncthreads();
        if (tid < 64) {
            atomicAdd(&g_stats[3 * 128 + tid], ssum[tid]);
            atomicAdd(&g_stats[3 * 128 + 64 + tid], ssq[tid]);
        }
    }
}

// ---------------- FFN via mma.sync: out = x2 + relu(bn(x2)@W1+b1)@W2 + b2 ------
// 256 threads (8 warps), dynamic smem, 2 CTAs/SM. Residual from staged fp16.
// which==0: source g_h2 (fp32); which==1: source g_e2h (fp16 direct copy).
__global__ void __launch_bounds__(256) k_ffn_mma(
    int which,
    int set,    // 2 (h) or 3 (e)
    const float* __restrict__ W1, const float* __restrict__ b1,
    const float* __restrict__ W2, const float* __restrict__ b2,
    const float* __restrict__ gamma, const float* __restrict__ beta,
    float inv, int rows, float* __restrict__ out) {
    const int LDA = 72, LDB1 = 136, LDB2 = 72;
    extern __shared__ char smraw[];
    __half* sB1 = (__half*)smraw;                       // 17408 B
    __half* sB2 = (__half*)(smraw + 17408);             // 18432 B
    __half* sA  = (__half*)(smraw + 35840);             // 8 x [16*72] = 18432 B
    float* sb1 = (float*)(smraw + 54272);               // 512 B
    float* sb2 = (float*)(smraw + 54784);               // 256 B
    float* sc  = (float*)(smraw + 55040);               // 256 B
    float* sh  = (float*)(smraw + 55296);               // 256 B

    int tid = threadIdx.x, wid = tid >> 5, lane = tid & 31;
    bn_fold_smem(tid, set, gamma, beta, inv, sc, sh);
    __syncthreads();
    for (int i = tid; i < 64 * 128; i += 256) {
        int k = i >> 7, n = i & 127;
        sB1[k * LDB1 + n] = __float2half(sc[k] * W1[i]);
    }
    for (int i = tid; i < 128 * 64; i += 256) {
        int k = i >> 6, n = i & 63;
        sB2[k * LDB2 + n] = __float2half(W2[i]);
    }
    if (tid < 128) {   // bias1 fold
        float acc = b1[tid];
#pragma unroll 8
        for (int k = 0; k < 64; k++) acc += sh[k] * W1[k * 128 + tid];
        sb1[tid] = acc;
    }
    if (tid < 64) sb2[tid] = b2[tid];
    __syncthreads();

    __half* aBuf = sA + wid * 16 * 72;
    uint32_t aU = smem_u32(aBuf);
    uint32_t b1U = smem_u32(sB1);
    uint32_t b2U = smem_u32(sB2);
    int cg = lane & 15;
    uint32_t aLdAddr = aU + (uint32_t)(((lane & 15) * LDA + ((lane >> 4) << 3)) * 2);
    uint32_t bRow = (uint32_t)(lane & 15);
    uint32_t bColOff = (uint32_t)((lane >> 4) << 3);
    int rq = lane >> 2;

    int ngroups = (rows + 15) >> 4;
    int gw = blockIdx.x * 8 + wid;
    int gstride = gridDim.x * 8;
    for (int g = gw; g < ngroups; g += gstride) {
        int rbase = g << 4;
        int rsub = lane >> 4;
        if (which == 0) {
#pragma unroll
            for (int j = 0; j < 8; j++) {
                int rloc = rsub + j * 2;
                int row = rbase + rloc; if (row >= rows) row = rows - 1;
                float4 v = *(const float4*)(g_h2 + (size_t)row * 64 + cg * 4);
                __half* dstp = aBuf + rloc * LDA + cg * 4;
                *(__half2*)(dstp) = __floats2half2_rn(v.x, v.y);
                *(__half2*)(dstp + 2) = __floats2half2_rn(v.z, v.w);
            }
        } else {
#pragma unroll
            for (int j = 0; j < 8; j++) {
                int rloc = rsub + j * 2;
                int row = rbase + rloc; if (row >= rows) row = rows - 1;
                uint2 v = *(const uint2*)(g_e2h + (size_t)row * 64 + cg * 4);
                *(uint2*)(aBuf + rloc * LDA + cg * 4) = v;
            }
        }
        __syncwarp();

        uint32_t afr[4][4];
#pragma unroll
        for (int kt = 0; kt < 4; kt++)
            ldsm_x4(afr[kt], aLdAddr + (uint32_t)(kt * 16 * 2));

        float c1[16][4];
#pragma unroll
        for (int nt = 0; nt < 16; nt++) { c1[nt][0] = c1[nt][1] = c1[nt][2] = c1[nt][3] = 0.f; }
#pragma unroll
        for (int ntp = 0; ntp < 8; ntp++) {
#pragma unroll
            for (int kt = 0; kt < 4; kt++) {
                uint32_t b[4];
                ldsm_x4t(b, b1U + (uint32_t)((((kt * 16) + bRow) * LDB1 + ntp * 16 + bColOff) * 2));
                mma_16816(c1[2 * ntp],     afr[kt], b[0], b[1]);
                mma_16816(c1[2 * ntp + 1], afr[kt], b[2], b[3]);
            }
        }

        uint32_t a2[8][4];
#pragma unroll
        for (int nt = 0; nt < 16; nt++) {
            int n0 = nt * 8 + 2 * (lane & 3);
            float bx = sb1[n0], by = sb1[n0 + 1];
            __half2 lo = __floats2half2_rn(fmaxf(c1[nt][0] + bx, 0.f),
                                           fmaxf(c1[nt][1] + by, 0.f));
            __half2 hi = __floats2half2_rn(fmaxf(c1[nt][2] + bx, 0.f),
                                           fmaxf(c1[nt][3] + by, 0.f));
            int kt2 = nt >> 1, base = (nt & 1) * 2;
            a2[kt2][base]     = *reinterpret_cast<uint32_t*>(&lo);
            a2[kt2][base + 1] = *reinterpret_cast<uint32_t*>(&hi);
        }

        float c2[8][4];
#pragma unroll
        for (int nt = 0; nt < 8; nt++) { c2[nt][0] = c2[nt][1] = c2[nt][2] = c2[nt][3] = 0.f; }
#pragma unroll
        for (int ntp = 0; ntp < 4; ntp++) {
#pragma unroll
            for (int kt = 0; kt < 8; kt++) {
                uint32_t b[4];
                ldsm_x4t(b, b2U + (uint32_t)((((kt * 16) + bRow) * LDB2 + ntp * 16 + bColOff) * 2));
                mma_16816(c2[2 * ntp],     a2[kt], b[0], b[1]);
                mma_16816(c2[2 * ntp + 1], a2[kt], b[2], b[3]);
            }
        }

        int r0 = rbase + rq;
        int r1 = r0 + 8;
#pragma unroll
        for (int nt = 0; nt < 8; nt++) {
            int n = nt * 8 + 2 * (lane & 3);
            float bx = sb2[n], by = sb2[n + 1];
            if (r0 < rows) {
                float2 xv = __half22float2(*(__half2*)(aBuf + rq * LDA + n));
                *(float2*)(out + (size_t)r0 * 64 + n) =
                    make_float2(xv.x + bx + c2[nt][0], xv.y + by + c2[nt][1]);
            }
            if (r1 < rows) {
                float2 xv = __half22float2(*(__half2*)(aBuf + (rq + 8) * LDA + n));
                *(float2*)(out + (size_t)r1 * 64 + n) =
                    make_float2(xv.x + bx + c2[nt][2], xv.y + by + c2[nt][3]);
            }
        }
        __syncwarp();
    }
}

// ---------------- host launcher -------------------------------------------------
extern "C" void kernel_launch(void* const* d_in, const int* in_sizes, int n_in,
                              void* d_out, int out_size) {
    int xAw, xAb, xBw, xBb, xCw, xCb, xDw, xDb, xEw, xEb;
    if (in_sizes[5] == 64) {  // dict order: Aw,Ab,Bw,Bb,Cw,Cb,Dw,Db,Ew,Eb
        xAw = 4; xAb = 5; xBw = 6; xBb = 7; xCw = 8; xCb = 9;
        xDw = 10; xDb = 11; xEw = 12; xEb = 13;
    } else {                  // signature order: Aw,Bw,Cw,Dw,Ew,Ab,Bb,Cb,Db,Eb
        xAw = 4; xBw = 5; xCw = 6; xDw = 7; xEw = 8;
        xAb = 9; xBb = 10; xCb = 11; xDb = 12; xEb = 13;
    }
    const float* h   = (const float*)d_in[0];
    const float* e   = (const float*)d_in[1];
    const int*   src = (const int*)d_in[2];
    const int*   dst = (const int*)d_in[3];
    const float* Aw = (const float*)d_in[xAw]; const float* Ab = (const float*)d_in[xAb];
    const float* Bw = (const float*)d_in[xBw]; const float* Bb = (const float*)d_in[xBb];
    const float* Cw = (const float*)d_in[xCw]; const float* Cb = (const float*)d_in[xCb];
    const float* Dw = (const float*)d_in[xDw]; const float* Db = (const float*)d_in[xDb];
    const float* Ew = (const float*)d_in[xEw]; const float* Eb = (const float*)d_in[xEb];
    const float* g1h = (const float*)d_in[14]; const float* g1e = (const float*)d_in[15];
    const float* g2h = (const float*)d_in[16]; const float* g2e = (const float*)d_in[17];
    const float* b1h = (const float*)d_in[18]; const float* b1e = (const float*)d_in[19];
    const float* b2h = (const float*)d_in[20]; const float* b2e = (const float*)d_in[21];
    const float* Wh1 = (const float*)d_in[22]; const float* bh1 = (const float*)d_in[23];
    const float* Wh2 = (const float*)d_in[24]; const float* bh2 = (const float*)d_in[25];
    const float* We1 = (const float*)d_in[26]; const float* be1 = (const float*)d_in[27];
    const float* We2 = (const float*)d_in[28]; const float* be2 = (const float*)d_in[29];
    float* out = (float*)d_out;

    int N = in_sizes[0] / 64;
    int E = in_sizes[2];
    float invN = 1.0f / (float)N, invE = 1.0f / (float)E;

    cudaFuncSetAttribute(k_node_mma, cudaFuncAttributeMaxDynamicSharedMemorySize, 55296);
    cudaFuncSetAttribute(k_ffn_mma, cudaFuncAttributeMaxDynamicSharedMemorySize, 55552);

    k_zero<<<1, 512>>>();                                                 // 0
    k_stats2<<<2560, 256>>>(h, N, e, E);                                  // 1
    k_node_mma<<<391, 256, 55296>>>(h, Aw, Bw, Cw, Dw, Ab, Bb, Cb, Db,
                                    g1h, b1h, invN, N);                   // 2
    k_edge_mma<<<2960, 128>>>(e, src, dst, Ew, Eb, g1e, b1e, invE, E);    // 3 <- profile
    k_h2s<<<2560, 256>>>(h, N, E);                                        // 4
    k_ffn_mma<<<296, 256, 55552>>>(0, 2, Wh1, bh1, Wh2, bh2, g2h, b2h, invN, N, out);   // 5
    k_ffn_mma<<<296, 256, 55552>>>(1, 3, We1, be1, We2, be2, g2e, b2e, invE, E,
                                   out + (size_t)N * 64);                 // 6
}

// round 16
// speedup vs baseline: 1.1326x; 1.0124x over previous
#include <cuda_runtime.h>
#include <cuda_fp16.h>
#include <cstdint>

#define FULLMASK 0xffffffffu

// Problem sizes (fixed by the dataset)
#define CN 50000
#define CE 800000

// ---------------- scratch (device globals; no cudaMalloc allowed) -------------
__device__ __align__(16) float g_Ah[CN * 64];
__device__ __align__(16) __half g_BCh[CN * 128]; // fp16 interleaved [B0,C0,B1,C1,...]
__device__ __align__(16) __half g_Dh[CN * 64];   // fp16
__device__ __align__(16) float g_h2[CN * 64];
__device__ __align__(16) float g_sx[CN * 128];   // interleaved [ss0,ssh0,ss1,ssh1,...]
__device__ __align__(16) __half g_e2h[CE * 64];  // e after residual, fp16
__device__ float g_stats[4 * 128]; // [set][sum(64) | sumsq(64)]

// ================= mma.sync / ldmatrix helpers (base sm_103 ISA) ===============
__device__ __forceinline__ uint32_t smem_u32(const void* p) {
    return (uint32_t)__cvta_generic_to_shared(p);
}

__device__ __forceinline__ void ldsm_x4(uint32_t (&r)[4], uint32_t addr) {
    asm volatile("ldmatrix.sync.aligned.m8n8.x4.shared.b16 {%0,%1,%2,%3}, [%4];"
                 : "=r"(r[0]), "=r"(r[1]), "=r"(r[2]), "=r"(r[3]) : "r"(addr));
}

// x4 transposed: loads TWO n8k16 B fragments at once.
__device__ __forceinline__ void ldsm_x4t(uint32_t (&b)[4], uint32_t addr) {
    asm volatile("ldmatrix.sync.aligned.m8n8.x4.trans.shared.b16 {%0,%1,%2,%3}, [%4];"
                 : "=r"(b[0]), "=r"(b[1]), "=r"(b[2]), "=r"(b[3]) : "r"(addr));
}

__device__ __forceinline__ void mma_16816(float (&c)[4], const uint32_t (&a)[4],
                                          uint32_t b0, uint32_t b1) {
    asm volatile(
        "mma.sync.aligned.m16n8k16.row.col.f32.f16.f16.f32 "
        "{%0,%1,%2,%3}, {%4,%5,%6,%7}, {%8,%9}, {%0,%1,%2,%3};"
        : "+f"(c[0]), "+f"(c[1]), "+f"(c[2]), "+f"(c[3])
        : "r"(a[0]), "r"(a[1]), "r"(a[2]), "r"(a[3]), "r"(b0), "r"(b1));
}

// helper: compute per-block BN scale/shift into smem (64 threads participate)
__device__ __forceinline__ void bn_fold_smem(int tid, int set,
                                             const float* __restrict__ gamma,
                                             const float* __restrict__ beta,
                                             float inv, float* sc, float* sh) {
    if (tid < 64) {
        float mean = g_stats[set * 128 + tid] * inv;
        float var = g_stats[set * 128 + 64 + tid] * inv - mean * mean;
        float s = gamma[tid] * rsqrtf(var + 1e-5f);
        sc[tid] = s;
        sh[tid] = beta[tid] - mean * s;
    }
}

// ---------------- zero stats accumulators --------------------------------------
__global__ void k_zero() {
    g_stats[threadIdx.x] = 0.f;
}

// ---------------- column mean/var stats for BOTH h and e -----------------------
__global__ __launch_bounds__(256) void k_stats2(const float* __restrict__ h, int hrows,
                                                const float* __restrict__ e, int erows) {
    __shared__ float ssum[64], ssq[64];
    int tid = threadIdx.x;
    bool isE = blockIdx.x >= 512;
    const float* __restrict__ x = isE ? e : h;
    int rows = isE ? erows : hrows;
    int set = isE ? 1 : 0;
    int bid = isE ? blockIdx.x - 512 : blockIdx.x;
    int nb = isE ? gridDim.x - 512 : 512;
    if (tid < 64) { ssum[tid] = 0.f; ssq[tid] = 0.f; }
    __syncthreads();
    int cg = tid & 15;
    int r = (bid * 256 + tid) >> 4;
    int rstride = (nb * 256) >> 4;
    float4 s = make_float4(0, 0, 0, 0), q = make_float4(0, 0, 0, 0);
    for (; r < rows; r += rstride) {
        float4 v = *(const float4*)(x + (size_t)r * 64 + cg * 4);
        s.x += v.x; s.y += v.y; s.z += v.z; s.w += v.w;
        q.x += v.x * v.x; q.y += v.y * v.y; q.z += v.z * v.z; q.w += v.w * v.w;
    }
    atomicAdd(&ssum[cg * 4 + 0], s.x); atomicAdd(&ssum[cg * 4 + 1], s.y);
    atomicAdd(&ssum[cg * 4 + 2], s.z); atomicAdd(&ssum[cg * 4 + 3], s.w);
    atomicAdd(&ssq[cg * 4 + 0], q.x);  atomicAdd(&ssq[cg * 4 + 1], q.y);
    atomicAdd(&ssq[cg * 4 + 2], q.z);  atomicAdd(&ssq[cg * 4 + 3], q.w);
    __syncthreads();
    if (tid < 64) {
        atomicAdd(&g_stats[set * 128 + tid], ssum[tid]);
        atomicAdd(&g_stats[set * 128 + 64 + tid], ssq[tid]);
    }
}

// ---------------- node linears via mma ------------------------------------------
__global__ __launch_bounds__(256) void k_node_mma(
    const float* __restrict__ h,
    const float* __restrict__ Aw, const float* __restrict__ Bw,
    const float* __restrict__ Cw, const float* __restrict__ Dw,
    const float* __restrict__ Ab, const float* __restrict__ Bb,
    const float* __restrict__ Cb, const float* __restrict__ Db,
    const float* __restrict__ g1h, const float* __restrict__ b1h,
    float invN, int rows) {
    extern __shared__ char smraw[];
    __half* sW = (__half*)smraw;                         // [64][264]
    __half* sA = (__half*)(smraw + 64 * 264 * 2);        // 8 warps x [16][72]
    float* sc = (float*)(smraw + 64 * 264 * 2 + 8 * 16 * 72 * 2);
    float* sh = sc + 64;
    float* sBias = sh + 64;                              // [4][64] order B,C,A,D
    int tid = threadIdx.x, wid = tid >> 5, lane = tid & 31;

    bn_fold_smem(tid, 0, g1h, b1h, invN, sc, sh);
    __syncthreads();
    for (int i = tid; i < 4 * 4096; i += 256) {
        int m = i >> 12, idx = i & 4095, k = idx >> 6, n = idx & 63;
        const float* W = m == 0 ? Bw : m == 1 ? Cw : m == 2 ? Aw : Dw;
        sW[k * 264 + m * 64 + n] = __float2half(sc[k] * W[idx]);
    }
    {
        int m = tid >> 6, n = tid & 63;
        const float* W = m == 0 ? Bw : m == 1 ? Cw : m == 2 ? Aw : Dw;
        const float* bb = m == 0 ? Bb : m == 1 ? Cb : m == 2 ? Ab : Db;
        float acc = bb[n];
#pragma unroll 8
        for (int k = 0; k < 64; k++) acc += sh[k] * W[k * 64 + n];
        sBias[tid] = acc;
    }
    __syncthreads();

    __half* aBuf = sA + wid * 16 * 72;
    uint32_t aU = smem_u32(aBuf);
    uint32_t wU = smem_u32(sW);
    uint32_t aLd = aU + (uint32_t)(((lane & 15) * 72 + ((lane >> 4) << 3)) * 2);
    uint32_t bRow = lane & 15;
    uint32_t bColOff = (uint32_t)((lane >> 4) << 3);
    int cg = lane & 15, rsub = lane >> 4;
    int ntiles = (rows + 15) >> 4;
    for (int t = blockIdx.x * 8 + wid; t < ntiles; t += gridDim.x * 8) {
        int rbase = t << 4;
#pragma unroll
        for (int j = 0; j < 8; j++) {
            int rloc = rsub + j * 2;
            int row = rbase + rloc; if (row >= rows) row = rows - 1;
            float4 v = *(const float4*)(h + (size_t)row * 64 + cg * 4);
            __half2 h0 = __floats2half2_rn(v.x, v.y);
            __half2 h1 = __floats2half2_rn(v.z, v.w);
            *(uint2*)(aBuf + rloc * 72 + cg * 4) =
                make_uint2(*(uint32_t*)&h0, *(uint32_t*)&h1);
        }
        __syncwarp();
        uint32_t afr[4][4];
#pragma unroll
        for (int kt = 0; kt < 4; kt++) ldsm_x4(afr[kt], aLd + kt * 32);
        int r0 = rbase + (lane >> 2), r1 = r0 + 8;
#pragma unroll
        for (int p = 0; p < 2; p++) {
            float c[16][4];
#pragma unroll
            for (int nt = 0; nt < 16; nt++) { c[nt][0] = c[nt][1] = c[nt][2] = c[nt][3] = 0.f; }
#pragma unroll
            for (int ntp = 0; ntp < 8; ntp++) {
#pragma unroll
                for (int kt = 0; kt < 4; kt++) {
                    uint32_t b[4];
                    ldsm_x4t(b, wU + (uint32_t)(((kt * 16 + bRow) * 264 + p * 128 + ntp * 16 + bColOff) * 2));
                    mma_16816(c[2 * ntp],     afr[kt], b[0], b[1]);
                    mma_16816(c[2 * ntp + 1], afr[kt], b[2], b[3]);
                }
            }
            if (p == 0) {
#pragma unroll
                for (int nt = 0; nt < 8; nt++) {
                    int col = nt * 8 + 2 * (lane & 3);
                    float2 bB = *(const float2*)(sBias + col);
                    float2 bC = *(const float2*)(sBias + 64 + col);
                    if (r0 < rows) {
                        __half2 h0 = __floats2half2_rn(c[nt][0] + bB.x, c[nt + 8][0] + bC.x);
                        __half2 h1 = __floats2half2_rn(c[nt][1] + bB.y, c[nt + 8][1] + bC.y);
                        __half2* dp = (__half2*)(g_BCh + (size_t)r0 * 128 + 2 * col);
                        dp[0] = h0; dp[1] = h1;
                    }
                    if (r1 < rows) {
                        __half2 h0 = __floats2half2_rn(c[nt][2] + bB.x, c[nt + 8][2] + bC.x);
                        __half2 h1 = __floats2half2_rn(c[nt][3] + bB.y, c[nt + 8][3] + bC.y);
                        __half2* dp = (__half2*)(g_BCh + (size_t)r1 * 128 + 2 * col);
                        dp[0] = h0; dp[1] = h1;
                    }
                }
            } else {
#pragma unroll
                for (int nt = 0; nt < 8; nt++) {
                    int col = nt * 8 + 2 * (lane & 3);
                    float2 bia = *(const float2*)(sBias + 128 + col);
                    if (r0 < rows)
                        *(float2*)(g_Ah + (size_t)r0 * 64 + col) =
                            make_float2(c[nt][0] + bia.x, c[nt][1] + bia.y);
                    if (r1 < rows)
                        *(float2*)(g_Ah + (size_t)r1 * 64 + col) =
                            make_float2(c[nt][2] + bia.x, c[nt][3] + bia.y);
                }
#pragma unroll
                for (int nt = 8; nt < 16; nt++) {
                    int col = (nt & 7) * 8 + 2 * (lane & 3);
                    float2 bia = *(const float2*)(sBias + 192 + col);
                    if (r0 < rows)
                        *(__half2*)(g_Dh + (size_t)r0 * 64 + col) =
                            __floats2half2_rn(c[nt][0] + bia.x, c[nt][1] + bia.y);
                    if (r1 < rows)
                        *(__half2*)(g_Dh + (size_t)r1 * 64 + col) =
                            __floats2half2_rn(c[nt][2] + bia.x, c[nt][3] + bia.y);
                }
            }
        }
        float4 z4 = make_float4(0.f, 0.f, 0.f, 0.f);
#pragma unroll
        for (int nt = 0; nt < 8; nt++) {
            int off = nt * 16 + (lane & 3) * 4;
            if (r0 < rows) *(float4*)(g_sx + (size_t)r0 * 128 + off) = z4;
            if (r1 < rows) *(float4*)(g_sx + (size_t)r1 * 128 + off) = z4;
        }
        __syncwarp();
    }
}

// ---------------- fused edge kernel (r12 best config) ---------------------------
// 128 threads, 8 CTAs/SM (64 regs). Split-N epilogue; per-tile B ldsm; fp16
// gathers; residual e from the fp16 staged tile; e2 fp16; float4 atomics.
__global__ void __launch_bounds__(128, 8) k_edge_mma(
    const float* __restrict__ e, const int* __restrict__ src, const int* __restrict__ dst,
    const float* __restrict__ Ew, const float* __restrict__ Eb,
    const float* __restrict__ g1e, const float* __restrict__ b1e,
    float invE, int ecount) {
    __shared__ __half sW[64 * 72];
    __shared__ __half sA[4][16 * 72];
    __shared__ float sc[64], sh[64], sb[64];
    int tid = threadIdx.x, wid = tid >> 5, lane = tid & 31;

    bn_fold_smem(tid, 1, g1e, b1e, invE, sc, sh);
    __syncthreads();
    for (int i = tid; i < 4096; i += 128) {
        int k = i >> 6, n = i & 63;
        sW[k * 72 + n] = __float2half(sc[k] * Ew[i]);
    }
    if (tid < 64) {
        float acc = Eb[tid];
#pragma unroll 8
        for (int k = 0; k < 64; k++) acc += sh[k] * Ew[k * 64 + tid];
        sb[tid] = acc;
    }
    __syncthreads();

    uint32_t aU = smem_u32(&sA[wid][0]);
    uint32_t wU = smem_u32(sW);
    uint32_t aLd = aU + (uint32_t)(((lane & 15) * 72 + ((lane >> 4) << 3)) * 2);
    uint32_t bRow = lane & 15;
    uint32_t bColOff = (uint32_t)((lane >> 4) << 3);
    int cg = lane & 15, rsub = lane >> 4;
    int rq = lane >> 2;
    int ntiles = ecount >> 4;
    for (int t = blockIdx.x * 4 + wid; t < ntiles; t += gridDim.x * 4) {
        int ebase = t << 4;
#pragma unroll
        for (int j = 0; j < 8; j++) {
            int rloc = rsub + j * 2;
            float4 v = *(const float4*)(e + (size_t)(ebase + rloc) * 64 + cg * 4);
            __half2 h0 = __floats2half2_rn(v.x, v.y);
            __half2 h1 = __floats2half2_rn(v.z, v.w);
            *(uint2*)(&sA[wid][rloc * 72 + cg * 4]) =
                make_uint2(*(uint32_t*)&h0, *(uint32_t*)&h1);
        }
        __syncwarp();
        uint32_t afr[4][4];
#pragma unroll
        for (int kt = 0; kt < 4; kt++) ldsm_x4(afr[kt], aLd + kt * 32);
        int r0 = ebase + rq, r1 = r0 + 8;
        int sI0 = src[r0], dI0 = dst[r0], sI1 = src[r1], dI1 = dst[r1];
#pragma unroll
        for (int half = 0; half < 2; half++) {
            float c[4][4];
#pragma unroll
            for (int nt = 0; nt < 4; nt++) { c[nt][0] = c[nt][1] = c[nt][2] = c[nt][3] = 0.f; }
#pragma unroll
            for (int ntp = 0; ntp < 2; ntp++) {
#pragma unroll
                for (int kt = 0; kt < 4; kt++) {
                    uint32_t b[4];
                    ldsm_x4t(b, wU + (uint32_t)(((kt * 16 + bRow) * 72 + (half * 2 + ntp) * 16 + bColOff) * 2));
                    mma_16816(c[2 * ntp],     afr[kt], b[0], b[1]);
                    mma_16816(c[2 * ntp + 1], afr[kt], b[2], b[3]);
                }
            }
#pragma unroll
            for (int nt = 0; nt < 4; nt++) {
                int c0 = (half * 4 + nt) * 8 + 2 * (lane & 3);
                float2 bia = *(const float2*)(sb + c0);
                uint2 raw0 = *(const uint2*)(g_BCh + (size_t)sI0 * 128 + 2 * c0);
                uint2 raw1 = *(const uint2*)(g_BCh + (size_t)sI1 * 128 + 2 * c0);
                float2 bc00 = __half22float2(*(__half2*)&raw0.x);
                float2 bc01 = __half22float2(*(__half2*)&raw0.y);
                float2 bc10 = __half22float2(*(__half2*)&raw1.x);
                float2 bc11 = __half22float2(*(__half2*)&raw1.y);
                float2 dh0 = __half22float2(*(const __half2*)(g_Dh + (size_t)dI0 * 64 + c0));
                float2 dh1 = __half22float2(*(const __half2*)(g_Dh + (size_t)dI1 * 64 + c0));
                float en00 = c[nt][0] + bia.x + bc00.y + dh0.x;
                float en01 = c[nt][1] + bia.y + bc01.y + dh0.y;
                float en10 = c[nt][2] + bia.x + bc10.y + dh1.x;
                float en11 = c[nt][3] + bia.y + bc11.y + dh1.y;
                float2 ev0 = __half22float2(*(__half2*)(&sA[wid][rq * 72 + c0]));
                float2 ev1 = __half22float2(*(__half2*)(&sA[wid][(rq + 8) * 72 + c0]));
                *(__half2*)(g_e2h + (size_t)r0 * 64 + c0) =
                    __floats2half2_rn(ev0.x + en00, ev0.y + en01);
                *(__half2*)(g_e2h + (size_t)r1 * 64 + c0) =
                    __floats2half2_rn(ev1.x + en10, ev1.y + en11);
                float sg00 = 1.f / (1.f + __expf(-en00));
                float sg01 = 1.f / (1.f + __expf(-en01));
                float sg10 = 1.f / (1.f + __expf(-en10));
                float sg11 = 1.f / (1.f + __expf(-en11));
                atomicAdd((float4*)(g_sx + (size_t)dI0 * 128 + 2 * c0),
                          make_float4(sg00, bc00.x * sg00, sg01, bc01.x * sg01));
                atomicAdd((float4*)(g_sx + (size_t)dI1 * 128 + 2 * c0),
                          make_float4(sg10, bc10.x * sg10, sg11, bc11.x * sg11));
            }
        }
        __syncwarp();
    }
}

// ---------------- h2 = h + Ah + ssh/(ss+eps) + set2 stats; e2 stats (set 3) ----
__global__ __launch_bounds__(256) void k_h2s(const float* __restrict__ h, int hrows, int erows) {
    int tid = threadIdx.x;
    if (blockIdx.x < 512) {
        int lane = tid & 31;
        int warp = (blockIdx.x * 256 + tid) >> 5;
        int nw = (512 * 256) >> 5;
        int c = lane * 2;
        float st_s0 = 0.f, st_s1 = 0.f, st_q0 = 0.f, st_q1 = 0.f;
        for (int r = warp; r < hrows; r += nw) {
            size_t o = (size_t)r * 64 + c;
            float2 hv = *(const float2*)(h + o);
            float2 ah = *(const float2*)(g_Ah + o);
            float4 sx = *(const float4*)(g_sx + (size_t)r * 128 + 2 * c);
            float v0 = hv.x + ah.x + sx.y / (sx.x + 1e-10f);
            float v1 = hv.y + ah.y + sx.w / (sx.z + 1e-10f);
            *(float2*)(g_h2 + o) = make_float2(v0, v1);
            st_s0 += v0; st_q0 += v0 * v0;
            st_s1 += v1; st_q1 += v1 * v1;
        }
        atomicAdd(&g_stats[2 * 128 + c], st_s0);
        atomicAdd(&g_stats[2 * 128 + c + 1], st_s1);
        atomicAdd(&g_stats[2 * 128 + 64 + c], st_q0);
        atomicAdd(&g_stats[2 * 128 + 64 + c + 1], st_q1);
    } else {
        __shared__ float ssum[64], ssq[64];
        if (tid < 64) { ssum[tid] = 0.f; ssq[tid] = 0.f; }
        __syncthreads();
        int bid = blockIdx.x - 512, nb = gridDim.x - 512;
        int cg = tid & 15;
        int r = (bid * 256 + tid) >> 4;
        int rstride = (nb * 256) >> 4;
        float4 s = make_float4(0, 0, 0, 0), q = make_float4(0, 0, 0, 0);
        for (; r < erows; r += rstride) {
            uint2 raw = *(const uint2*)(g_e2h + (size_t)r * 64 + cg * 4);
            float2 f01 = __half22float2(*(__half2*)&raw.x);
            float2 f23 = __half22float2(*(__half2*)&raw.y);
            s.x += f01.x; s.y += f01.y; s.z += f23.x; s.w += f23.y;
            q.x += f01.x * f01.x; q.y += f01.y * f01.y;
            q.z += f23.x * f23.x; q.w += f23.y * f23.y;
        }
        atomicAdd(&ssum[cg * 4 + 0], s.x); atomicAdd(&ssum[cg * 4 + 1], s.y);
        atomicAdd(&ssum[cg * 4 + 2], s.z); atomicAdd(&ssum[cg * 4 + 3], s.w);
        atomicAdd(&ssq[cg * 4 + 0], q.x);  atomicAdd(&ssq[cg * 4 + 1], q.y);
        atomicAdd(&ssq[cg * 4 + 2], q.z);  atomicAdd(&ssq[cg * 4 + 3], q.w);
        __syncthreads();
        if (tid < 64) {
            atomicAdd(&g_stats[3 * 128 + tid], ssum[tid]);
            atomicAdd(&g_stats[3 * 128 + 64 + tid], ssq[tid]);
        }
    }
}

// ---------------- FFN via mma.sync: 32 rows/warp-iter, shared B2 fragments -----
// 256 threads (8 warps), 2 CTAs/SM. GEMM1 per 16-row group with early repack
// (c1 lives 8 regs); GEMM2 shares each B fragment across both groups.
__global__ void __launch_bounds__(256, 2) k_ffn_mma(
    int which,
    int set,    // 2 (h) or 3 (e)
    const float* __restrict__ W1, const float* __restrict__ b1,
    const float* __restrict__ W2, const float* __restrict__ b2,
    const float* __restrict__ gamma, const float* __restrict__ beta,
    float inv, int rows, float* __restrict__ out) {
    const int LDA = 72, LDB1 = 136, LDB2 = 72;
    extern __shared__ char smraw[];
    __half* sB1 = (__half*)smraw;                       // 17408 B
    __half* sB2 = (__half*)(smraw + 17408);             // 18432 B
    __half* sA  = (__half*)(smraw + 35840);             // 8 x [32*72] = 36864 B
    float* sb1 = (float*)(smraw + 72704);               // 512 B
    float* sb2 = (float*)(smraw + 73216);               // 256 B
    float* sc  = (float*)(smraw + 73472);               // 256 B
    float* sh  = (float*)(smraw + 73728);               // 256 B

    int tid = threadIdx.x, wid = tid >> 5, lane = tid & 31;
    bn_fold_smem(tid, set, gamma, beta, inv, sc, sh);
    __syncthreads();
    for (int i = tid; i < 64 * 128; i += 256) {
        int k = i >> 7, n = i & 127;
        sB1[k * LDB1 + n] = __float2half(sc[k] * W1[i]);
    }
    for (int i = tid; i < 128 * 64; i += 256) {
        int k = i >> 6, n = i & 63;
        sB2[k * LDB2 + n] = __float2half(W2[i]);
    }
    if (tid < 128) {
        float acc = b1[tid];
#pragma unroll 8
        for (int k = 0; k < 64; k++) acc += sh[k] * W1[k * 128 + tid];
        sb1[tid] = acc;
    }
    if (tid < 64) sb2[tid] = b2[tid];
    __syncthreads();

    __half* aBuf = sA + wid * 32 * 72;
    uint32_t aU = smem_u32(aBuf);
    uint32_t b1U = smem_u32(sB1);
    uint32_t b2U = smem_u32(sB2);
    int cg = lane & 15;
    uint32_t aLdAddr = aU + (uint32_t)(((lane & 15) * LDA + ((lane >> 4) << 3)) * 2);
    uint32_t bRow = (uint32_t)(lane & 15);
    uint32_t bColOff = (uint32_t)((lane >> 4) << 3);
    int rq = lane >> 2;
    int rsub = lane >> 4;

    int ngroups = (rows + 31) >> 5;   // 32-row groups
    int gw = blockIdx.x * 8 + wid;
    int gstride = gridDim.x * 8;
    for (int g = gw; g < ngroups; g += gstride) {
        int rbase = g << 5;
        // ---- stage 32 rows fp16 ----
        if (which == 0) {
#pragma unroll
            for (int j = 0; j < 16; j++) {
                int rloc = rsub + j * 2;
                int row = rbase + rloc; if (row >= rows) row = rows - 1;
                float4 v = *(const float4*)(g_h2 + (size_t)row * 64 + cg * 4);
                __half2 h0 = __floats2half2_rn(v.x, v.y);
                __half2 h1 = __floats2half2_rn(v.z, v.w);
                *(uint2*)(aBuf + rloc * LDA + cg * 4) =
                    make_uint2(*(uint32_t*)&h0, *(uint32_t*)&h1);
            }
        } else {
#pragma unroll
            for (int j = 0; j < 16; j++) {
                int rloc = rsub + j * 2;
                int row = rbase + rloc; if (row >= rows) row = rows - 1;
                uint2 v = *(const uint2*)(g_e2h + (size_t)row * 64 + cg * 4);
                *(uint2*)(aBuf + rloc * LDA + cg * 4) = v;
            }
        }
        __syncwarp();

        // ---- GEMM1 per 16-row group with early repack ----
        uint32_t a2g[2][8][4];
#pragma unroll
        for (int G = 0; G < 2; G++) {
            uint32_t afr[4][4];
#pragma unroll
            for (int kt = 0; kt < 4; kt++)
                ldsm_x4(afr[kt], aLdAddr + (uint32_t)((G * 16 * LDA + kt * 16) * 2));
#pragma unroll
            for (int ntp = 0; ntp < 8; ntp++) {
                float c1[2][4];
                c1[0][0] = c1[0][1] = c1[0][2] = c1[0][3] = 0.f;
                c1[1][0] = c1[1][1] = c1[1][2] = c1[1][3] = 0.f;
#pragma unroll
                for (int kt = 0; kt < 4; kt++) {
                    uint32_t b[4];
                    ldsm_x4t(b, b1U + (uint32_t)((((kt * 16) + bRow) * LDB1 + ntp * 16 + bColOff) * 2));
                    mma_16816(c1[0], afr[kt], b[0], b[1]);
                    mma_16816(c1[1], afr[kt], b[2], b[3]);
                }
#pragma unroll
                for (int sub = 0; sub < 2; sub++) {
                    int n0 = (2 * ntp + sub) * 8 + 2 * (lane & 3);
                    float bx = sb1[n0], by = sb1[n0 + 1];
                    __half2 lo = __floats2half2_rn(fmaxf(c1[sub][0] + bx, 0.f),
                                                   fmaxf(c1[sub][1] + by, 0.f));
                    __half2 hi = __floats2half2_rn(fmaxf(c1[sub][2] + bx, 0.f),
                                                   fmaxf(c1[sub][3] + by, 0.f));
                    a2g[G][ntp][sub * 2]     = *reinterpret_cast<uint32_t*>(&lo);
                    a2g[G][ntp][sub * 2 + 1] = *reinterpret_cast<uint32_t*>(&hi);
                }
            }
        }

        // ---- GEMM2 with B fragments shared across both groups ----
#pragma unroll
        for (int ntp = 0; ntp < 4; ntp++) {
            float c2[2][2][4];   // [G][sub]
#pragma unroll
            for (int G = 0; G < 2; G++)
#pragma unroll
                for (int sub = 0; sub < 2; sub++)
                    c2[G][sub][0] = c2[G][sub][1] = c2[G][sub][2] = c2[G][sub][3] = 0.f;
#pragma unroll
            for (int kt = 0; kt < 8; kt++) {
                uint32_t b[4];
                ldsm_x4t(b, b2U + (uint32_t)((((kt * 16) + bRow) * LDB2 + ntp * 16 + bColOff) * 2));
                mma_16816(c2[0][0], a2g[0][kt], b[0], b[1]);
                mma_16816(c2[0][1], a2g[0][kt], b[2], b[3]);
                mma_16816(c2[1][0], a2g[1][kt], b[0], b[1]);
                mma_16816(c2[1][1], a2g[1][kt], b[2], b[3]);
            }
#pragma unroll
            for (int G = 0; G < 2; G++) {
                int r0 = rbase + G * 16 + rq;
                int r1 = r0 + 8;
#pragma unroll
                for (int sub = 0; sub < 2; sub++) {
                    int n = (2 * ntp + sub) * 8 + 2 * (lane & 3);
                    float bx = sb2[n], by = sb2[n + 1];
                    if (r0 < rows) {
                        float2 xv = __half22float2(*(__half2*)(aBuf + (G * 16 + rq) * LDA + n));
                        *(float2*)(out + (size_t)r0 * 64 + n) =
                            make_float2(xv.x + bx + c2[G][sub][0], xv.y + by + c2[G][sub][1]);
                    }
                    if (r1 < rows) {
                        float2 xv = __half22float2(*(__half2*)(aBuf + (G * 16 + rq + 8) * LDA + n));
                        *(float2*)(out + (size_t)r1 * 64 + n) =
                            make_float2(xv.x + bx + c2[G][sub][2], xv.y + by + c2[G][sub][3]);
                    }
                }
            }
        }
        __syncwarp();
    }
}

// ---------------- host launcher -------------------------------------------------
extern "C" void kernel_launch(void* const* d_in, const int* in_sizes, int n_in,
                              void* d_out, int out_size) {
    int xAw, xAb, xBw, xBb, xCw, xCb, xDw, xDb, xEw, xEb;
    if (in_sizes[5] == 64) {  // dict order: Aw,Ab,Bw,Bb,Cw,Cb,Dw,Db,Ew,Eb
        xAw = 4; xAb = 5; xBw = 6; xBb = 7; xCw = 8; xCb = 9;
        xDw = 10; xDb = 11; xEw = 12; xEb = 13;
    } else {                  // signature order: Aw,Bw,Cw,Dw,Ew,Ab,Bb,Cb,Db,Eb
        xAw = 4; xBw = 5; xCw = 6; xDw = 7; xEw = 8;
        xAb = 9; xBb = 10; xCb = 11; xDb = 12; xEb = 13;
    }
    const float* h   = (const float*)d_in[0];
    const float* e   = (const float*)d_in[1];
    const int*   src = (const int*)d_in[2];
    const int*   dst = (const int*)d_in[3];
    const float* Aw = (const float*)d_in[xAw]; const float* Ab = (const float*)d_in[xAb];
    const float* Bw = (const float*)d_in[xBw]; const float* Bb = (const float*)d_in[xBb];
    const float* Cw = (const float*)d_in[xCw]; const float* Cb = (const float*)d_in[xCb];
    const float* Dw = (const float*)d_in[xDw]; const float* Db = (const float*)d_in[xDb];
    const float* Ew = (const float*)d_in[xEw]; const float* Eb = (const float*)d_in[xEb];
    const float* g1h = (const float*)d_in[14]; const float* g1e = (const float*)d_in[15];
    const float* g2h = (const float*)d_in[16]; const float* g2e = (const float*)d_in[17];
    const float* b1h = (const float*)d_in[18]; const float* b1e = (const float*)d_in[19];
    const float* b2h = (const float*)d_in[20]; const float* b2e = (const float*)d_in[21];
    const float* Wh1 = (const float*)d_in[22]; const float* bh1 = (const float*)d_in[23];
    const float* Wh2 = (const float*)d_in[24]; const float* bh2 = (const float*)d_in[25];
    const float* We1 = (const float*)d_in[26]; const float* be1 = (const float*)d_in[27];
    const float* We2 = (const float*)d_in[28]; const float* be2 = (const float*)d_in[29];
    float* out = (float*)d_out;

    int N = in_sizes[0] / 64;
    int E = in_sizes[2];
    float invN = 1.0f / (float)N, invE = 1.0f / (float)E;

    cudaFuncSetAttribute(k_node_mma, cudaFuncAttributeMaxDynamicSharedMemorySize, 55296);
    cudaFuncSetAttribute(k_ffn_mma, cudaFuncAttributeMaxDynamicSharedMemorySize, 73984);

    k_zero<<<1, 512>>>();                                                 // 0
    k_stats2<<<2560, 256>>>(h, N, e, E);                                  // 1
    k_node_mma<<<391, 256, 55296>>>(h, Aw, Bw, Cw, Dw, Ab, Bb, Cb, Db,
                                    g1h, b1h, invN, N);                   // 2
    k_edge_mma<<<2960, 128>>>(e, src, dst, Ew, Eb, g1e, b1e, invE, E);    // 3 <- profile
    k_h2s<<<2560, 256>>>(h, N, E);                                        // 4
    k_ffn_mma<<<296, 256, 73984>>>(0, 2, Wh1, bh1, Wh2, bh2, g2h, b2h, invN, N, out);   // 5
    k_ffn_mma<<<296, 256, 73984>>>(1, 3, We1, be1, We2, be2, g2e, b2e, invE, E,
                                   out + (size_t)N * 64);                 // 6
}